// round 1
// baseline (speedup 1.0000x reference)
#include <cuda_runtime.h>
#include <cstdint>

#define T_LEN 1024
#define NBATCH 1024
#define HID 64
#define MROWS 8

// Scratch: inter-layer activation sequences [T][B][H] fp32, double-buffered.
__device__ float g_bufA[(size_t)T_LEN * NBATCH * HID];
__device__ float g_bufB[(size_t)T_LEN * NBATCH * HID];

// ---------- packed f32x2 helpers (Blackwell FFMA2) ----------
static __device__ __forceinline__ unsigned long long pack2(float x, float y) {
    unsigned long long r;
    asm("mov.b64 %0, {%1, %2};" : "=l"(r) : "f"(x), "f"(y));
    return r;
}
static __device__ __forceinline__ void unpack2(unsigned long long v, float &x, float &y) {
    asm("mov.b64 {%0, %1}, %2;" : "=f"(x), "=f"(y) : "l"(v));
}
static __device__ __forceinline__ void ffma2(unsigned long long &d,
                                             unsigned long long a,
                                             unsigned long long b) {
    asm("fma.rn.f32x2 %0, %1, %2, %0;" : "+l"(d) : "l"(a), "l"(b));
}

// ---------- cp.async helpers ----------
static __device__ __forceinline__ void cp_async16(void* sdst, const void* gsrc) {
    unsigned sa = (unsigned)__cvta_generic_to_shared(sdst);
    asm volatile("cp.async.ca.shared.global [%0], [%1], 16;\n" :: "r"(sa), "l"(gsrc));
}
static __device__ __forceinline__ void cp_commit() {
    asm volatile("cp.async.commit_group;\n" ::: "memory");
}
static __device__ __forceinline__ void cp_wait0() {
    asm volatile("cp.async.wait_group 0;\n" ::: "memory");
}

// ---------- activations (accurate fast-math, err ~1e-6) ----------
static __device__ __forceinline__ float sigf(float x) {
    float e = __expf(-x);
    return __fdividef(1.f, 1.f + e);
}
static __device__ __forceinline__ float tanh_f(float x) {
    x = fminf(fmaxf(x, -15.f), 15.f);
    float e = __expf(-2.f * x);
    return __fdividef(1.f - e, 1.f + e);
}

// ---------- embedding gather: g_bufA[t][b][h] = emb[x[b][t]][h] ----------
__global__ void gather_emb_kernel(const int* __restrict__ x, const float* __restrict__ emb) {
    unsigned e4 = blockIdx.x * blockDim.x + threadIdx.x;  // float4 index, T*B*16 total
    int h4 = e4 & 15;
    int b  = (e4 >> 4) & (NBATCH - 1);
    int t  = e4 >> 14;
    int xi = x[(size_t)b * T_LEN + t];
    float4 v = ((const float4*)emb)[xi * (HID / 4) + h4];
    ((float4*)g_bufA)[e4] = v;
}

// ---------- one LSTM layer over all T, batch-parallel across blocks ----------
// 256 threads: thread j owns output column (gate g=j>>6, hidden n=j&63) for all
// M=8 batch rows; its 128 fp32 weights live in registers for the whole layer.
__global__ void __launch_bounds__(256, 1) lstm_layer_kernel(
    int layer, int in_sel, int out_sel, int is_last,
    const float* __restrict__ Wi, const float* __restrict__ Wf,
    const float* __restrict__ Wg, const float* __restrict__ Wo,
    const float* __restrict__ bi, const float* __restrict__ bf,
    const float* __restrict__ bg, const float* __restrict__ bo,
    const float* __restrict__ init_h, const int* __restrict__ lengths,
    const float* __restrict__ head_w, const float* __restrict__ head_b,
    float* __restrict__ logits)
{
    __shared__ __align__(16) float catx[2][MROWS][HID];   // x-part of cat, double buffered
    __shared__ __align__(16) float cath[MROWS][HID];      // h-part of cat (h_{t-1})
    __shared__ float pre_s[MROWS][256];                   // gate preactivations

    const int j = threadIdx.x;
    const int g = j >> 6;        // gate: 0=i 1=f 2=g 3=o
    const int n = j & 63;        // hidden index
    const int mbase = blockIdx.x * MROWS;

    const float* inp  = in_sel  ? g_bufB : g_bufA;
    float*       outp = out_sel ? g_bufB : g_bufA;

    // Load this thread's weight row (128 floats) into registers as 64 f32x2 packs.
    const float* Wsel =
        (g == 0 ? Wi : (g == 1 ? Wf : (g == 2 ? Wg : Wo))) + ((size_t)(layer * HID + n)) * 128;
    unsigned long long w2[64];
#pragma unroll
    for (int i = 0; i < 32; i++) {
        ulonglong2 v = ((const ulonglong2*)Wsel)[i];
        w2[2 * i]     = v.x;
        w2[2 * i + 1] = v.y;
    }
    const float bias = (g == 0 ? bi : (g == 1 ? bf : (g == 2 ? bg : bo)))[layer * HID + n];

    // Elementwise phase identity: thread j also owns rows (2g, 2g+1), hidden n.
    const int mA = 2 * g, mB = 2 * g + 1;
    const int lenA = lengths[mbase + mA];
    const int lenB = lengths[mbase + mB];
    const float h0 = tanhf(init_h[layer * HID + n]);
    float cA = 0.f, cB = 0.f, hA = h0, hB = h0;
    cath[mA][n] = h0;
    cath[mB][n] = h0;

    // Prefetch x(0)
    if (j < 128) {
        int r = j >> 4, c4 = j & 15;
        cp_async16(&catx[0][r][c4 * 4], inp + ((size_t)mbase + r) * HID + c4 * 4);
    }
    cp_commit();

    for (int t = 0; t < T_LEN; t++) {
        cp_wait0();
        __syncthreads();  // x(t) landed, h(t-1) written
        const int buf = t & 1;
        if (t + 1 < T_LEN && j < 128) {
            int r = j >> 4, c4 = j & 15;
            cp_async16(&catx[buf ^ 1][r][c4 * 4],
                       inp + ((size_t)(t + 1) * NBATCH + mbase + r) * HID + c4 * 4);
        }
        cp_commit();

        // GEMM: pre[m][j] = bias + sum_k cat[m][k] * W[j][k]   (k=0..63 x, 64..127 h)
        unsigned long long a0[MROWS], a1[MROWS];
#pragma unroll
        for (int m = 0; m < MROWS; m++) {
            a0[m] = pack2(bias, 0.f);
            a1[m] = pack2(0.f, 0.f);
        }
#pragma unroll
        for (int m = 0; m < MROWS; m++) {
            const ulonglong2* cx = (const ulonglong2*)catx[buf][m];
#pragma unroll
            for (int q = 0; q < 16; q++) {
                ulonglong2 v = cx[q];                       // floats 4q..4q+3 (broadcast LDS)
                ffma2(a0[m], w2[2 * q],     v.x);
                ffma2(a1[m], w2[2 * q + 1], v.y);
            }
            const ulonglong2* ch = (const ulonglong2*)cath[m];
#pragma unroll
            for (int q = 0; q < 16; q++) {
                ulonglong2 v = ch[q];                       // floats 64+4q..64+4q+3
                ffma2(a0[m], w2[32 + 2 * q], v.x);
                ffma2(a1[m], w2[33 + 2 * q], v.y);
            }
        }
#pragma unroll
        for (int m = 0; m < MROWS; m++) {
            float x0, y0, x1, y1;
            unpack2(a0[m], x0, y0);
            unpack2(a1[m], x1, y1);
            pre_s[m][j] = (x0 + x1) + (y0 + y1);
        }
        __syncthreads();

        // Elementwise LSTM cell for rows mA, mB at hidden n
        {
            float pi = pre_s[mA][n], pf = pre_s[mA][64 + n];
            float pg = pre_s[mA][128 + n], po = pre_s[mA][192 + n];
            float it = sigf(pi), ft = sigf(pf), gt = tanh_f(pg), ot = sigf(po);
            float cn = ft * cA + it * gt;
            float hn = ot * tanh_f(cn);
            if (t < lenA) { cA = cn; hA = hn; }
            cath[mA][n] = hA;
        }
        {
            float pi = pre_s[mB][n], pf = pre_s[mB][64 + n];
            float pg = pre_s[mB][128 + n], po = pre_s[mB][192 + n];
            float it = sigf(pi), ft = sigf(pf), gt = tanh_f(pg), ot = sigf(po);
            float cn = ft * cB + it * gt;
            float hn = ot * tanh_f(cn);
            if (t < lenB) { cB = cn; hB = hn; }
            cath[mB][n] = hB;
        }
        if (!is_last) {
            outp[((size_t)t * NBATCH + mbase + mA) * HID + n] = hA;
            outp[((size_t)t * NBATCH + mbase + mB) * HID + n] = hB;
        }
    }

    if (is_last) {
        __syncthreads();  // final h in cath
        if (j < MROWS) {
            float s = 0.f;
#pragma unroll
            for (int k = 0; k < HID; k++) s += cath[j][k] * head_w[k];
            logits[mbase + j] = s + head_b[0];
        }
    }
}

extern "C" void kernel_launch(void* const* d_in, const int* in_sizes, int n_in,
                              void* d_out, int out_size) {
    const int*   x       = (const int*)d_in[0];
    const int*   lengths = (const int*)d_in[1];
    const float* emb     = (const float*)d_in[2];
    const float* Wi      = (const float*)d_in[3];
    const float* Wf      = (const float*)d_in[4];
    const float* Wg      = (const float*)d_in[5];
    const float* Wo      = (const float*)d_in[6];
    const float* bi      = (const float*)d_in[7];
    const float* bf      = (const float*)d_in[8];
    const float* bg      = (const float*)d_in[9];
    const float* bo      = (const float*)d_in[10];
    const float* init_h  = (const float*)d_in[11];
    const float* head_w  = (const float*)d_in[12];
    const float* head_b  = (const float*)d_in[13];
    float* logits = (float*)d_out;

    // 1) Embedding gather into bufA: [T][B][H]
    gather_emb_kernel<<<(T_LEN * NBATCH * (HID / 4)) / 256, 256>>>(x, emb);

    // 2) Five layer passes, ping-ponging bufA/bufB. Last layer emits logits.
    for (int l = 0; l < 5; l++) {
        int in_sel  = l & 1;
        int out_sel = in_sel ^ 1;
        int is_last = (l == 4) ? 1 : 0;
        lstm_layer_kernel<<<NBATCH / MROWS, 256>>>(
            l, in_sel, out_sel, is_last,
            Wi, Wf, Wg, Wo, bi, bf, bg, bo,
            init_h, lengths, head_w, head_b, logits);
    }
}

// round 2
// speedup vs baseline: 1.6936x; 1.6936x over previous
#include <cuda_runtime.h>
#include <cuda_bf16.h>
#include <cstdint>

#define T_LEN 1024
#define NB    1024
#define HID   64
#define MR    16          // batch rows per block
#define APITCH 136        // bf16 elements per A-row (272B, conflict-free ldmatrix)
#define PPITCH 264        // floats per pre-activation row

// Inter-layer activation sequences, bf16 hi/lo pairs packed 2-per-u32.
// [buf pair][hi/lo][T*B*32]
__device__ uint32_t g_seq[2][2][(size_t)T_LEN * NB * (HID / 2)];

// ---------------- helpers ----------------
static __device__ __forceinline__ uint16_t bfbits(__nv_bfloat16 h) {
    return __bfloat16_as_ushort(h);
}
// Split (a,b) fp32 pair into packed bf16 hi-pair (return) and lo-pair (*lo).
static __device__ __forceinline__ uint32_t bfsplit2(float a, float b, uint32_t* lo) {
    __nv_bfloat16 ha = __float2bfloat16(a), hb = __float2bfloat16(b);
    float ra = a - __bfloat162float(ha);
    float rb = b - __bfloat162float(hb);
    __nv_bfloat16 la = __float2bfloat16(ra), lb = __float2bfloat16(rb);
    *lo = ((uint32_t)bfbits(lb) << 16) | bfbits(la);
    return ((uint32_t)bfbits(hb) << 16) | bfbits(ha);
}

static __device__ __forceinline__ void ldsm4(uint32_t a[4], uint32_t addr) {
    asm volatile("ldmatrix.sync.aligned.m8n8.x4.shared.b16 {%0,%1,%2,%3}, [%4];"
                 : "=r"(a[0]), "=r"(a[1]), "=r"(a[2]), "=r"(a[3]) : "r"(addr));
}
static __device__ __forceinline__ void mma_bf16(float c[4], const uint32_t a[4],
                                                const uint32_t b[2]) {
    asm volatile(
        "mma.sync.aligned.m16n8k16.row.col.f32.bf16.bf16.f32 "
        "{%0,%1,%2,%3}, {%4,%5,%6,%7}, {%8,%9}, {%0,%1,%2,%3};"
        : "+f"(c[0]), "+f"(c[1]), "+f"(c[2]), "+f"(c[3])
        : "r"(a[0]), "r"(a[1]), "r"(a[2]), "r"(a[3]), "r"(b[0]), "r"(b[1]));
}

static __device__ __forceinline__ void cp_async16(void* sdst, const void* gsrc) {
    unsigned sa = (unsigned)__cvta_generic_to_shared(sdst);
    asm volatile("cp.async.ca.shared.global [%0], [%1], 16;\n" :: "r"(sa), "l"(gsrc));
}
static __device__ __forceinline__ void cp_commit() {
    asm volatile("cp.async.commit_group;\n" ::: "memory");
}
static __device__ __forceinline__ void cp_wait0() {
    asm volatile("cp.async.wait_group 0;\n" ::: "memory");
}

static __device__ __forceinline__ float sigf(float x) {
    float e = __expf(-x);
    return __fdividef(1.f, 1.f + e);
}
static __device__ __forceinline__ float tanh_f(float x) {
    x = fminf(fmaxf(x, -15.f), 15.f);
    float e = __expf(-2.f * x);
    return __fdividef(1.f - e, 1.f + e);
}

// ---------------- embedding gather -> g_seq[0] (bf16 hi/lo) ----------------
__global__ void gather_emb(const int* __restrict__ x, const float* __restrict__ emb) {
    size_t e = (size_t)blockIdx.x * 256 + threadIdx.x;   // over T*B*32
    int h2 = e & 31;
    int b  = (e >> 5) & (NB - 1);
    int t  = (int)(e >> 15);
    int xi = x[(size_t)b * T_LEN + t];
    float2 v = ((const float2*)(emb + (size_t)xi * HID))[h2];
    uint32_t lp, hp = bfsplit2(v.x, v.y, &lp);
    size_t o = ((size_t)t * NB + b) * (HID / 2) + h2;
    g_seq[0][0][o] = hp;
    g_seq[0][1][o] = lp;
}

// ---------------- LSTM layer: tensor-core GEMM per step ----------------
__global__ void __launch_bounds__(512, 1) lstm_layer(
    int layer, int in_sel, int is_last,
    const float* __restrict__ Wi, const float* __restrict__ Wf,
    const float* __restrict__ Wg, const float* __restrict__ Wo,
    const float* __restrict__ bi, const float* __restrict__ bf,
    const float* __restrict__ bg, const float* __restrict__ bo,
    const float* __restrict__ init_h, const int* __restrict__ lengths,
    const float* __restrict__ head_w, const float* __restrict__ head_b,
    float* __restrict__ logits)
{
    __shared__ __align__(16) uint16_t sA[2][2][MR * APITCH];  // [buf][hi/lo]
    __shared__ __align__(16) float sPre[MR * PPITCH];

    const int j    = threadIdx.x;
    const int lane = j & 31;
    const int w    = j >> 5;          // warp id == batch row m for elementwise
    const int m    = w;
    const int g    = lane >> 2;
    const int tig  = lane & 3;
    const int mbase = blockIdx.x * MR;
    const int out_sel = in_sel ^ 1;

    // ---- weight B-fragments (hi/lo) in registers, biases ----
    uint32_t whi[2][8][2], wlo[2][8][2];
    float be[2], bo_[2];
#pragma unroll
    for (int nt = 0; nt < 2; nt++) {
        int jo   = 16 * w + 8 * nt + g;       // output column for B frag
        int gate = jo >> 6, nc = jo & 63;
        const float* Wr =
            (gate == 0 ? Wi : gate == 1 ? Wf : gate == 2 ? Wg : Wo) +
            (size_t)(layer * HID + nc) * 128;
#pragma unroll
        for (int kt = 0; kt < 8; kt++) {
            int k0 = 16 * kt + 2 * tig;
            whi[nt][kt][0] = bfsplit2(Wr[k0],     Wr[k0 + 1], &wlo[nt][kt][0]);
            whi[nt][kt][1] = bfsplit2(Wr[k0 + 8], Wr[k0 + 9], &wlo[nt][kt][1]);
        }
        int je = 16 * w + 8 * nt + 2 * tig;   // bias cols for C frag (even/odd)
        int ge = je >> 6, ne = je & 63;
        const float* Be = (ge == 0 ? bi : ge == 1 ? bf : ge == 2 ? bg : bo);
        be[nt]  = Be[layer * HID + ne];
        int jo2 = je + 1;
        int go2 = jo2 >> 6, no2 = jo2 & 63;
        const float* Bo = (go2 == 0 ? bi : go2 == 1 ? bf : go2 == 2 ? bg : bo);
        bo_[nt] = Bo[layer * HID + no2];
    }

    // ---- elementwise state: thread owns (m, 2*lane) and (m, 2*lane+1) ----
    const int len = lengths[mbase + m];
    const int n0 = 2 * lane, n1 = 2 * lane + 1;
    float hst[2], cst[2] = {0.f, 0.f};
    hst[0] = tanh_f(init_h[layer * HID + n0]);
    hst[1] = tanh_f(init_h[layer * HID + n1]);

    // prefetch x(0) into buf0
    if (j < 256) {
        int pm = j >> 4, sub = j & 15, hl = sub >> 3, ch = sub & 7;
        cp_async16(&sA[0][hl][pm * APITCH + ch * 8],
                   &g_seq[in_sel][hl][((size_t)0 * NB + mbase + pm) * 32 + ch * 4]);
    }
    cp_commit();

    // h0 into buf0 h-half
    {
        uint32_t lp, hp = bfsplit2(hst[0], hst[1], &lp);
        *(uint32_t*)&sA[0][0][m * APITCH + 64 + n0] = hp;
        *(uint32_t*)&sA[0][1][m * APITCH + 64 + n0] = lp;
    }
    cp_wait0();
    __syncthreads();

    // ldmatrix per-thread base (row = lane&15, col base = (lane>=16)*8)
    const int arow = lane & 15;
    const int acol = (lane >> 4) * 8;

    for (int t = 0; t < T_LEN; t++) {
        const int buf = t & 1;
        if (t + 1 < T_LEN && j < 256) {
            int pm = j >> 4, sub = j & 15, hl = sub >> 3, ch = sub & 7;
            cp_async16(&sA[buf ^ 1][hl][pm * APITCH + ch * 8],
                       &g_seq[in_sel][hl][((size_t)(t + 1) * NB + mbase + pm) * 32 + ch * 4]);
        }
        cp_commit();

        // ---- GEMM: C[16 x 16(warp slice)] = A[16x128] * W ----
        float c0[4] = {be[0], bo_[0], be[0], bo_[0]};
        float c1[4] = {be[1], bo_[1], be[1], bo_[1]};
        uint32_t baseHi = (uint32_t)__cvta_generic_to_shared(
            &sA[buf][0][arow * APITCH + acol]);
        uint32_t baseLo = (uint32_t)__cvta_generic_to_shared(
            &sA[buf][1][arow * APITCH + acol]);
#pragma unroll
        for (int kt = 0; kt < 8; kt++) {
            uint32_t ah[4], al[4];
            ldsm4(ah, baseHi + kt * 32);
            ldsm4(al, baseLo + kt * 32);
            mma_bf16(c0, ah, whi[0][kt]);
            mma_bf16(c1, ah, whi[1][kt]);
            mma_bf16(c0, ah, wlo[0][kt]);
            mma_bf16(c1, ah, wlo[1][kt]);
            mma_bf16(c0, al, whi[0][kt]);
            mma_bf16(c1, al, whi[1][kt]);
        }
        {
            int col0 = 16 * w + 2 * tig;
            int col1 = col0 + 8;
            *(float2*)&sPre[g * PPITCH + col0]       = make_float2(c0[0], c0[1]);
            *(float2*)&sPre[(g + 8) * PPITCH + col0] = make_float2(c0[2], c0[3]);
            *(float2*)&sPre[g * PPITCH + col1]       = make_float2(c1[0], c1[1]);
            *(float2*)&sPre[(g + 8) * PPITCH + col1] = make_float2(c1[2], c1[3]);
        }
        __syncthreads();

        // ---- elementwise LSTM cell for (m, n0) and (m, n1) ----
        {
            float2 pi2 = *(const float2*)&sPre[m * PPITCH + n0];
            float2 pf2 = *(const float2*)&sPre[m * PPITCH + 64 + n0];
            float2 pg2 = *(const float2*)&sPre[m * PPITCH + 128 + n0];
            float2 po2 = *(const float2*)&sPre[m * PPITCH + 192 + n0];
            float pi_[2] = {pi2.x, pi2.y}, pf_[2] = {pf2.x, pf2.y};
            float pg_[2] = {pg2.x, pg2.y}, po_[2] = {po2.x, po2.y};
#pragma unroll
            for (int i = 0; i < 2; i++) {
                float it = sigf(pi_[i]), ft = sigf(pf_[i]);
                float gt = tanh_f(pg_[i]), ot = sigf(po_[i]);
                float cn = ft * cst[i] + it * gt;
                float hn = ot * tanh_f(cn);
                if (t < len) { cst[i] = cn; hst[i] = hn; }
            }
            uint32_t lp, hp = bfsplit2(hst[0], hst[1], &lp);
            *(uint32_t*)&sA[buf ^ 1][0][m * APITCH + 64 + n0] = hp;
            *(uint32_t*)&sA[buf ^ 1][1][m * APITCH + 64 + n0] = lp;
            if (!is_last) {
                size_t o = ((size_t)t * NB + mbase + m) * 32 + lane;
                g_seq[out_sel][0][o] = hp;
                g_seq[out_sel][1][o] = lp;
            }
        }
        cp_wait0();
        __syncthreads();
    }

    // ---- head on last layer ----
    if (is_last) {
        *(float2*)&sPre[m * HID + n0] = make_float2(hst[0], hst[1]);
        __syncthreads();
        if (j < MR) {
            float s = 0.f;
#pragma unroll
            for (int k = 0; k < HID; k++) s += sPre[j * HID + k] * head_w[k];
            logits[mbase + j] = s + head_b[0];
        }
    }
}

extern "C" void kernel_launch(void* const* d_in, const int* in_sizes, int n_in,
                              void* d_out, int out_size) {
    const int*   x       = (const int*)d_in[0];
    const int*   lengths = (const int*)d_in[1];
    const float* emb     = (const float*)d_in[2];
    const float* Wi      = (const float*)d_in[3];
    const float* Wf      = (const float*)d_in[4];
    const float* Wg      = (const float*)d_in[5];
    const float* Wo      = (const float*)d_in[6];
    const float* bi      = (const float*)d_in[7];
    const float* bf      = (const float*)d_in[8];
    const float* bg      = (const float*)d_in[9];
    const float* bo      = (const float*)d_in[10];
    const float* init_h  = (const float*)d_in[11];
    const float* head_w  = (const float*)d_in[12];
    const float* head_b  = (const float*)d_in[13];
    float* logits = (float*)d_out;

    gather_emb<<<(size_t)T_LEN * NB * 32 / 256, 256>>>(x, emb);

    for (int l = 0; l < 5; l++) {
        int in_sel  = l & 1;
        int is_last = (l == 4) ? 1 : 0;
        lstm_layer<<<NB / MR, 512>>>(
            l, in_sel, is_last,
            Wi, Wf, Wg, Wo, bi, bf, bg, bo,
            init_h, lengths, head_w, head_b, logits);
    }
}

// round 3
// speedup vs baseline: 2.3539x; 1.3899x over previous
#include <cuda_runtime.h>
#include <cuda_bf16.h>
#include <cstdint>

#define T_LEN 1024
#define NB    1024
#define HID   64
#define MR    16          // batch rows per block
#define NGRP  (NB / MR)   // 64 groups
#define NLAY  5
#define APITCH 136        // bf16 elements per A-row (272B, conflict-free ldmatrix)
#define PPITCH 264        // floats per pre-activation row

// Inter-layer activation sequences, bf16 hi/lo pairs packed 2-per-u32.
__device__ uint32_t g_seq[2][2][(size_t)T_LEN * NB * (HID / 2)];
// progress flag: latest timestep t whose h is globally visible, per (layer, group)
__device__ int g_prog[NLAY * NGRP];

// ---------------- helpers ----------------
static __device__ __forceinline__ uint16_t bfbits(__nv_bfloat16 h) {
    return __bfloat16_as_ushort(h);
}
static __device__ __forceinline__ uint32_t bfsplit2(float a, float b, uint32_t* lo) {
    __nv_bfloat16 ha = __float2bfloat16(a), hb = __float2bfloat16(b);
    float ra = a - __bfloat162float(ha);
    float rb = b - __bfloat162float(hb);
    __nv_bfloat16 la = __float2bfloat16(ra), lb = __float2bfloat16(rb);
    *lo = ((uint32_t)bfbits(lb) << 16) | bfbits(la);
    return ((uint32_t)bfbits(hb) << 16) | bfbits(ha);
}
static __device__ __forceinline__ void ldsm4(uint32_t a[4], uint32_t addr) {
    asm volatile("ldmatrix.sync.aligned.m8n8.x4.shared.b16 {%0,%1,%2,%3}, [%4];"
                 : "=r"(a[0]), "=r"(a[1]), "=r"(a[2]), "=r"(a[3]) : "r"(addr));
}
static __device__ __forceinline__ void mma_bf16(float c[4], const uint32_t a[4],
                                                const uint32_t b[2]) {
    asm volatile(
        "mma.sync.aligned.m16n8k16.row.col.f32.bf16.bf16.f32 "
        "{%0,%1,%2,%3}, {%4,%5,%6,%7}, {%8,%9}, {%0,%1,%2,%3};"
        : "+f"(c[0]), "+f"(c[1]), "+f"(c[2]), "+f"(c[3])
        : "r"(a[0]), "r"(a[1]), "r"(a[2]), "r"(a[3]), "r"(b[0]), "r"(b[1]));
}
// L2-only async copy (no L1 allocation: inter-block coherence via L2)
static __device__ __forceinline__ void cp_async16(void* sdst, const void* gsrc) {
    unsigned sa = (unsigned)__cvta_generic_to_shared(sdst);
    asm volatile("cp.async.cg.shared.global [%0], [%1], 16;\n" :: "r"(sa), "l"(gsrc));
}
static __device__ __forceinline__ void cp_commit() {
    asm volatile("cp.async.commit_group;\n" ::: "memory");
}
static __device__ __forceinline__ void cp_wait0() {
    asm volatile("cp.async.wait_group 0;\n" ::: "memory");
}
static __device__ __forceinline__ float sigf(float x) {
    float e = __expf(-x);
    return __fdividef(1.f, 1.f + e);
}
static __device__ __forceinline__ float tanh_f(float x) {
    x = fminf(fmaxf(x, -15.f), 15.f);
    float e = __expf(-2.f * x);
    return __fdividef(1.f - e, 1.f + e);
}
static __device__ __forceinline__ void publish(int* p, int v) {
    asm volatile("st.release.gpu.global.b32 [%0], %1;" :: "l"(p), "r"(v) : "memory");
}
static __device__ __forceinline__ int acq_load(const int* p) {
    int v;
    asm volatile("ld.acquire.gpu.global.b32 %0, [%1];" : "=r"(v) : "l"(p) : "memory");
    return v;
}

// ---------------- flag reset ----------------
__global__ void reset_flags() {
    if (threadIdx.x < NLAY * NGRP) g_prog[threadIdx.x] = -1;
}

// ---------------- embedding gather -> g_seq[0] ----------------
__global__ void gather_emb(const int* __restrict__ x, const float* __restrict__ emb) {
    size_t e = (size_t)blockIdx.x * 256 + threadIdx.x;   // over T*B*32
    int h2 = e & 31;
    int b  = (e >> 5) & (NB - 1);
    int t  = (int)(e >> 15);
    int xi = x[(size_t)b * T_LEN + t];
    float2 v = ((const float2*)(emb + (size_t)xi * HID))[h2];
    uint32_t lp, hp = bfsplit2(v.x, v.y, &lp);
    size_t o = ((size_t)t * NB + b) * (HID / 2) + h2;
    g_seq[0][0][o] = hp;
    g_seq[0][1][o] = lp;
}

// ---------------- fused pipelined LSTM: grid = NLAY*NGRP, layer-major ----------------
__global__ void __launch_bounds__(512, 1) lstm_fused(
    const float* __restrict__ Wi, const float* __restrict__ Wf,
    const float* __restrict__ Wg, const float* __restrict__ Wo,
    const float* __restrict__ bi, const float* __restrict__ bf,
    const float* __restrict__ bg, const float* __restrict__ bo,
    const float* __restrict__ init_h, const int* __restrict__ lengths,
    const float* __restrict__ head_w, const float* __restrict__ head_b,
    float* __restrict__ logits)
{
    __shared__ __align__(16) uint16_t sA[2][2][MR * APITCH];  // [buf][hi/lo]
    __shared__ __align__(16) float sPre[MR * PPITCH];

    const int layer = blockIdx.x >> 6;     // 0..4  (low ids = early layers)
    const int grp   = blockIdx.x & (NGRP - 1);
    const int in_sel  = layer & 1;
    const int out_sel = in_sel ^ 1;
    const int is_last = (layer == NLAY - 1);
    const int has_src = (layer > 0);

    const int j    = threadIdx.x;
    const int lane = j & 31;
    const int w    = j >> 5;
    const int m    = w;
    const int g    = lane >> 2;
    const int tig  = lane & 3;
    const int mbase = grp * MR;

    int* my_flag  = &g_prog[layer * NGRP + grp];
    const int* src_flag = &g_prog[(layer - 1) * NGRP + grp];
    int avail_c = -1;   // thread0's cached view of producer progress

    // ---- weight B-fragments (hi/lo) in registers, biases ----
    uint32_t whi[2][8][2], wlo[2][8][2];
    float be[2], bo_[2];
#pragma unroll
    for (int nt = 0; nt < 2; nt++) {
        int jo   = 16 * w + 8 * nt + g;
        int gate = jo >> 6, nc = jo & 63;
        const float* Wr =
            (gate == 0 ? Wi : gate == 1 ? Wf : gate == 2 ? Wg : Wo) +
            (size_t)(layer * HID + nc) * 128;
#pragma unroll
        for (int kt = 0; kt < 8; kt++) {
            int k0 = 16 * kt + 2 * tig;
            whi[nt][kt][0] = bfsplit2(Wr[k0],     Wr[k0 + 1], &wlo[nt][kt][0]);
            whi[nt][kt][1] = bfsplit2(Wr[k0 + 8], Wr[k0 + 9], &wlo[nt][kt][1]);
        }
        int je = 16 * w + 8 * nt + 2 * tig;
        int ge = je >> 6, ne = je & 63;
        const float* Be = (ge == 0 ? bi : ge == 1 ? bf : ge == 2 ? bg : bo);
        be[nt]  = Be[layer * HID + ne];
        int jo2 = je + 1;
        int go2 = jo2 >> 6, no2 = jo2 & 63;
        const float* Bo = (go2 == 0 ? bi : go2 == 1 ? bf : go2 == 2 ? bg : bo);
        bo_[nt] = Bo[layer * HID + no2];
    }

    // ---- elementwise state ----
    const int len = lengths[mbase + m];
    const int n0 = 2 * lane, n1 = 2 * lane + 1;
    float hst[2], cst[2] = {0.f, 0.f};
    hst[0] = tanh_f(init_h[layer * HID + n0]);
    hst[1] = tanh_f(init_h[layer * HID + n1]);

    // gate x(0),x(1) availability for layers > 0
    if (has_src && j == 0) {
        int v = avail_c;
        while (v < 1) {
            v = acq_load(src_flag);
            if (v < 1) __nanosleep(60);
        }
        avail_c = v;
    }
    __syncthreads();

    // prefetch x(0) into buf0
    if (j < 256) {
        int pm = j >> 4, sub = j & 15, hl = sub >> 3, ch = sub & 7;
        cp_async16(&sA[0][hl][pm * APITCH + ch * 8],
                   &g_seq[in_sel][hl][((size_t)0 * NB + mbase + pm) * 32 + ch * 4]);
    }
    cp_commit();
    {
        uint32_t lp, hp = bfsplit2(hst[0], hst[1], &lp);
        *(uint32_t*)&sA[0][0][m * APITCH + 64 + n0] = hp;
        *(uint32_t*)&sA[0][1][m * APITCH + 64 + n0] = lp;
    }
    cp_wait0();
    __syncthreads();

    const int arow = lane & 15;
    const int acol = (lane >> 4) * 8;

    for (int t = 0; t < T_LEN; t++) {
        const int buf = t & 1;
        if (t + 1 < T_LEN && j < 256) {
            int pm = j >> 4, sub = j & 15, hl = sub >> 3, ch = sub & 7;
            cp_async16(&sA[buf ^ 1][hl][pm * APITCH + ch * 8],
                       &g_seq[in_sel][hl][((size_t)(t + 1) * NB + mbase + pm) * 32 + ch * 4]);
        }
        cp_commit();

        // ---- GEMM: C[16 x 16(warp slice)] = A[16x128] * W (3-term bf16 split) ----
        float c0[4] = {be[0], bo_[0], be[0], bo_[0]};
        float c1[4] = {be[1], bo_[1], be[1], bo_[1]};
        uint32_t baseHi = (uint32_t)__cvta_generic_to_shared(
            &sA[buf][0][arow * APITCH + acol]);
        uint32_t baseLo = (uint32_t)__cvta_generic_to_shared(
            &sA[buf][1][arow * APITCH + acol]);
#pragma unroll
        for (int kt = 0; kt < 8; kt++) {
            uint32_t ah[4], al[4];
            ldsm4(ah, baseHi + kt * 32);
            ldsm4(al, baseLo + kt * 32);
            mma_bf16(c0, ah, whi[0][kt]);
            mma_bf16(c1, ah, whi[1][kt]);
            mma_bf16(c0, ah, wlo[0][kt]);
            mma_bf16(c1, ah, wlo[1][kt]);
            mma_bf16(c0, al, whi[0][kt]);
            mma_bf16(c1, al, whi[1][kt]);
        }
        {
            int col0 = 16 * w + 2 * tig;
            int col1 = col0 + 8;
            *(float2*)&sPre[g * PPITCH + col0]       = make_float2(c0[0], c0[1]);
            *(float2*)&sPre[(g + 8) * PPITCH + col0] = make_float2(c0[2], c0[3]);
            *(float2*)&sPre[g * PPITCH + col1]       = make_float2(c1[0], c1[1]);
            *(float2*)&sPre[(g + 8) * PPITCH + col1] = make_float2(c1[2], c1[3]);
        }
        __syncthreads();   // mid barrier: C visible; also orders h(t-1) stores+fences
        // publish h up to t-1 (odd steps only; those were fenced at step t-1)
        if (!is_last && j == 0 && t >= 2 && (t & 1) == 0) publish(my_flag, t - 1);

        // ---- elementwise LSTM cell ----
        {
            float2 pi2 = *(const float2*)&sPre[m * PPITCH + n0];
            float2 pf2 = *(const float2*)&sPre[m * PPITCH + 64 + n0];
            float2 pg2 = *(const float2*)&sPre[m * PPITCH + 128 + n0];
            float2 po2 = *(const float2*)&sPre[m * PPITCH + 192 + n0];
            float pi_[2] = {pi2.x, pi2.y}, pf_[2] = {pf2.x, pf2.y};
            float pg_[2] = {pg2.x, pg2.y}, po_[2] = {po2.x, po2.y};
#pragma unroll
            for (int i = 0; i < 2; i++) {
                float it = sigf(pi_[i]), ft = sigf(pf_[i]);
                float gt = tanh_f(pg_[i]), ot = sigf(po_[i]);
                float cn = ft * cst[i] + it * gt;
                float hn = ot * tanh_f(cn);
                if (t < len) { cst[i] = cn; hst[i] = hn; }
            }
            uint32_t lp, hp = bfsplit2(hst[0], hst[1], &lp);
            *(uint32_t*)&sA[buf ^ 1][0][m * APITCH + 64 + n0] = hp;
            *(uint32_t*)&sA[buf ^ 1][1][m * APITCH + 64 + n0] = lp;
            if (!is_last) {
                size_t o = ((size_t)t * NB + mbase + m) * 32 + lane;
                g_seq[out_sel][0][o] = hp;
                g_seq[out_sel][1][o] = lp;
            }
        }
        if (!is_last && (t & 1)) __threadfence();   // make h(t-1),h(t) gpu-visible
        cp_wait0();
        // gate next iteration's prefetch of x(t+2)
        if (has_src && j == 0) {
            int need = t + 2 < T_LEN ? t + 2 : T_LEN - 1;
            int v = avail_c;
            while (v < need) {
                v = acq_load(src_flag);
                if (v < need) __nanosleep(60);
            }
            avail_c = v;
        }
        __syncthreads();   // bottom barrier
    }
    if (!is_last && j == 0) publish(my_flag, T_LEN - 1);

    // ---- head on last layer ----
    if (is_last) {
        *(float2*)&sPre[m * HID + n0] = make_float2(hst[0], hst[1]);
        __syncthreads();
        if (j < MR) {
            float s = 0.f;
#pragma unroll
            for (int k = 0; k < HID; k++) s += sPre[j * HID + k] * head_w[k];
            logits[mbase + j] = s + head_b[0];
        }
    }
}

extern "C" void kernel_launch(void* const* d_in, const int* in_sizes, int n_in,
                              void* d_out, int out_size) {
    const int*   x       = (const int*)d_in[0];
    const int*   lengths = (const int*)d_in[1];
    const float* emb     = (const float*)d_in[2];
    const float* Wi      = (const float*)d_in[3];
    const float* Wf      = (const float*)d_in[4];
    const float* Wg      = (const float*)d_in[5];
    const float* Wo      = (const float*)d_in[6];
    const float* bi      = (const float*)d_in[7];
    const float* bf      = (const float*)d_in[8];
    const float* bg      = (const float*)d_in[9];
    const float* bo      = (const float*)d_in[10];
    const float* init_h  = (const float*)d_in[11];
    const float* head_w  = (const float*)d_in[12];
    const float* head_b  = (const float*)d_in[13];
    float* logits = (float*)d_out;

    reset_flags<<<1, 512>>>();
    gather_emb<<<(size_t)T_LEN * NB * 32 / 256, 256>>>(x, emb);
    lstm_fused<<<NLAY * NGRP, 512>>>(
        Wi, Wf, Wg, Wo, bi, bf, bg, bo,
        init_h, lengths, head_w, head_b, logits);
}

// round 4
// speedup vs baseline: 2.7402x; 1.1641x over previous
#include <cuda_runtime.h>
#include <cuda_bf16.h>
#include <cstdint>

#define T_LEN 1024
#define NB    1024
#define HID   64
#define NLAY  5
#define NCTA_L 29          // CTAs per layer (one wave: 5*29=145 <= 148)
#define N3    6            // first 6 CTAs: 48 rows (3 mtiles); other 23: 32 rows
#define XPITCH 72          // halfwords per x/h row plane (144B, odd 16B multiple)
#define PPITCH 264         // floats per pre-activation row
#define SX_PLANE (48 * XPITCH)                    // 3456 halfwords
#define SH_BASE  (4 * SX_PLANE)                   // after 2 bufs x 2 (hi/lo) x-planes
#define SPRE_OFF ((SH_BASE + 2 * SX_PLANE) * 2)   // byte offset of sPre
#define SMEM_BYTES (SPRE_OFF + 48 * PPITCH * 4)   // 92160

// Inter-layer activation sequences, bf16 hi/lo pairs packed 2-per-u32.
__device__ uint32_t g_seq[2][2][(size_t)T_LEN * NB * (HID / 2)];
__device__ int g_prog[NLAY * NCTA_L];

// ---------------- helpers ----------------
static __device__ __forceinline__ uint16_t bfbits(__nv_bfloat16 h) {
    return __bfloat16_as_ushort(h);
}
static __device__ __forceinline__ uint32_t bfsplit2(float a, float b, uint32_t* lo) {
    __nv_bfloat16 ha = __float2bfloat16(a), hb = __float2bfloat16(b);
    float ra = a - __bfloat162float(ha);
    float rb = b - __bfloat162float(hb);
    __nv_bfloat16 la = __float2bfloat16(ra), lb = __float2bfloat16(rb);
    *lo = ((uint32_t)bfbits(lb) << 16) | bfbits(la);
    return ((uint32_t)bfbits(hb) << 16) | bfbits(ha);
}
static __device__ __forceinline__ void ldsm4(uint32_t a[4], uint32_t addr) {
    asm volatile("ldmatrix.sync.aligned.m8n8.x4.shared.b16 {%0,%1,%2,%3}, [%4];"
                 : "=r"(a[0]), "=r"(a[1]), "=r"(a[2]), "=r"(a[3]) : "r"(addr));
}
static __device__ __forceinline__ void mma_bf16(float c[4], const uint32_t a[4],
                                                const uint32_t b[2]) {
    asm volatile(
        "mma.sync.aligned.m16n8k16.row.col.f32.bf16.bf16.f32 "
        "{%0,%1,%2,%3}, {%4,%5,%6,%7}, {%8,%9}, {%0,%1,%2,%3};"
        : "+f"(c[0]), "+f"(c[1]), "+f"(c[2]), "+f"(c[3])
        : "r"(a[0]), "r"(a[1]), "r"(a[2]), "r"(a[3]), "r"(b[0]), "r"(b[1]));
}
static __device__ __forceinline__ void cp_async16(void* sdst, const void* gsrc) {
    unsigned sa = (unsigned)__cvta_generic_to_shared(sdst);
    asm volatile("cp.async.cg.shared.global [%0], [%1], 16;\n" :: "r"(sa), "l"(gsrc));
}
static __device__ __forceinline__ void cp_commit() {
    asm volatile("cp.async.commit_group;\n" ::: "memory");
}
static __device__ __forceinline__ void cp_wait0() {
    asm volatile("cp.async.wait_group 0;\n" ::: "memory");
}
static __device__ __forceinline__ float sigf(float x) {
    float e = __expf(-x);
    return __fdividef(1.f, 1.f + e);
}
static __device__ __forceinline__ float tanh_f(float x) {
    x = fminf(fmaxf(x, -15.f), 15.f);
    float e = __expf(-2.f * x);
    return __fdividef(1.f - e, 1.f + e);
}
static __device__ __forceinline__ void publish(int* p, int v) {
    asm volatile("st.release.gpu.global.b32 [%0], %1;" :: "l"(p), "r"(v) : "memory");
}
static __device__ __forceinline__ int acq_load(const int* p) {
    int v;
    asm volatile("ld.acquire.gpu.global.b32 %0, [%1];" : "=r"(v) : "l"(p) : "memory");
    return v;
}

// ---------------- embedding gather -> g_seq[0] (+ flag reset) ----------------
__global__ void gather_emb(const int* __restrict__ x, const float* __restrict__ emb) {
    if (blockIdx.x == 0 && threadIdx.x < NLAY * NCTA_L) g_prog[threadIdx.x] = -1;
    size_t e = (size_t)blockIdx.x * 256 + threadIdx.x;   // over T*B*32
    int h2 = e & 31;
    int b  = (e >> 5) & (NB - 1);
    int t  = (int)(e >> 15);
    int xi = x[(size_t)b * T_LEN + t];
    float2 v = ((const float2*)(emb + (size_t)xi * HID))[h2];
    uint32_t lp, hp = bfsplit2(v.x, v.y, &lp);
    size_t o = ((size_t)t * NB + b) * (HID / 2) + h2;
    g_seq[0][0][o] = hp;
    g_seq[0][1][o] = lp;
}

// ---------------- fused one-wave pipelined LSTM ----------------
__global__ void __launch_bounds__(512, 1) lstm_fused(
    const float* __restrict__ Wi, const float* __restrict__ Wf,
    const float* __restrict__ Wg, const float* __restrict__ Wo,
    const float* __restrict__ bi, const float* __restrict__ bf,
    const float* __restrict__ bg, const float* __restrict__ bo,
    const float* __restrict__ init_h, const int* __restrict__ lengths,
    const float* __restrict__ head_w, const float* __restrict__ head_b,
    float* __restrict__ logits)
{
    extern __shared__ __align__(16) uint16_t sm[];
    float* sPre = (float*)((char*)sm + SPRE_OFF);

    const int layer = blockIdx.x / NCTA_L;
    const int gi    = blockIdx.x - layer * NCTA_L;
    const int mc     = (gi < N3) ? 3 : 2;              // mtiles in this CTA
    const int mstart = (gi < N3) ? 48 * gi : 288 + 32 * (gi - N3);
    const int rows   = 16 * mc;
    const int nchunk = 256 * mc;                        // 16B cp.async chunks per buf
    const int in_sel  = layer & 1;
    const int out_sel = in_sel ^ 1;
    const int is_last = (layer == NLAY - 1);
    const int has_src = (layer > 0);

    const int j    = threadIdx.x;
    const int lane = j & 31;
    const int w    = j >> 5;
    const int g    = lane >> 2;
    const int tig  = lane & 3;
    const int arow = lane & 15;
    const int acol = (lane >> 4) * 8;

    int* my_flag        = &g_prog[layer * NCTA_L + gi];
    const int* src_flag = &g_prog[(layer - 1) * NCTA_L + gi];
    int avail_c = -1;

    // ---- weight B-fragments (hi/lo) in registers, biases ----
    uint32_t whi[2][8][2], wlo[2][8][2];
    float be[2], bo_[2];
#pragma unroll
    for (int nt = 0; nt < 2; nt++) {
        int jo   = 16 * w + 8 * nt + g;
        int gate = jo >> 6, nc = jo & 63;
        const float* Wr =
            (gate == 0 ? Wi : gate == 1 ? Wf : gate == 2 ? Wg : Wo) +
            (size_t)(layer * HID + nc) * 128;
#pragma unroll
        for (int kt = 0; kt < 8; kt++) {
            int k0 = 16 * kt + 2 * tig;
            whi[nt][kt][0] = bfsplit2(Wr[k0],     Wr[k0 + 1], &wlo[nt][kt][0]);
            whi[nt][kt][1] = bfsplit2(Wr[k0 + 8], Wr[k0 + 9], &wlo[nt][kt][1]);
        }
        int je = 16 * w + 8 * nt + 2 * tig;
        int ge = je >> 6, ne = je & 63;
        be[nt] = (ge == 0 ? bi : ge == 1 ? bf : ge == 2 ? bg : bo)[layer * HID + ne];
        int jo2 = je + 1;
        int go2 = jo2 >> 6, no2 = jo2 & 63;
        bo_[nt] = (go2 == 0 ? bi : go2 == 1 ? bf : go2 == 2 ? bg : bo)[layer * HID + no2];
    }

    // ---- cell state: thread owns pairs p = q*512+j, q<mc (m=p>>5, np=p&31) ----
    float hst[6], cst[6];
    int lenq[3];
#pragma unroll
    for (int q = 0; q < 3; q++) if (q < mc) {
        int p = q * 512 + j, ml = p >> 5, np = p & 31;
        lenq[q] = lengths[mstart + ml];
        hst[2 * q]     = tanh_f(init_h[layer * HID + 2 * np]);
        hst[2 * q + 1] = tanh_f(init_h[layer * HID + 2 * np + 1]);
        cst[2 * q] = 0.f; cst[2 * q + 1] = 0.f;
    }

    // gate x(0),x(1) for layers > 0
    if (has_src && j == 0) {
        int v = -1;
        while (v < 1) { v = acq_load(src_flag); if (v < 1) __nanosleep(60); }
        avail_c = v;
    }
    __syncthreads();

    // prefetch x(0) into sX buf0
#pragma unroll
    for (int q = 0; q < 2; q++) {
        int c = q * 512 + j;
        if (c < nchunk) {
            int r = c >> 4, sub = c & 15, hl = sub >> 3, ch = sub & 7;
            cp_async16(sm + hl * SX_PLANE + r * XPITCH + ch * 8,
                       &g_seq[in_sel][hl][((size_t)0 * NB + mstart + r) * 32 + ch * 4]);
        }
    }
    cp_commit();

    // h0 into sH
#pragma unroll
    for (int q = 0; q < 3; q++) if (q < mc) {
        int p = q * 512 + j, ml = p >> 5, np = p & 31;
        uint32_t lp, hp = bfsplit2(hst[2 * q], hst[2 * q + 1], &lp);
        *(uint32_t*)(sm + SH_BASE + 0 * SX_PLANE + ml * XPITCH + 2 * np) = hp;
        *(uint32_t*)(sm + SH_BASE + 1 * SX_PLANE + ml * XPITCH + 2 * np) = lp;
    }
    cp_wait0();
    __syncthreads();

    // prologue: prefetch x(1) into buf1, then x-GEMM(0) into cxa
#pragma unroll
    for (int q = 0; q < 2; q++) {
        int c = q * 512 + j;
        if (c < nchunk) {
            int r = c >> 4, sub = c & 15, hl = sub >> 3, ch = sub & 7;
            cp_async16(sm + (2 + hl) * SX_PLANE + r * XPITCH + ch * 8,
                       &g_seq[in_sel][hl][((size_t)1 * NB + mstart + r) * 32 + ch * 4]);
        }
    }
    cp_commit();

    float cxa[3][2][4];
#pragma unroll
    for (int mt = 0; mt < 3; mt++) if (mt < mc) {
#pragma unroll
        for (int nt = 0; nt < 2; nt++) {
            cxa[mt][nt][0] = be[nt]; cxa[mt][nt][1] = bo_[nt];
            cxa[mt][nt][2] = be[nt]; cxa[mt][nt][3] = bo_[nt];
        }
        uint32_t bHi = (uint32_t)__cvta_generic_to_shared(
            sm + 0 * SX_PLANE + (mt * 16 + arow) * XPITCH + acol);
        uint32_t bLo = (uint32_t)__cvta_generic_to_shared(
            sm + 1 * SX_PLANE + (mt * 16 + arow) * XPITCH + acol);
#pragma unroll
        for (int kt = 0; kt < 4; kt++) {
            uint32_t ah[4], al[4];
            ldsm4(ah, bHi + kt * 32);
            ldsm4(al, bLo + kt * 32);
            mma_bf16(cxa[mt][0], ah, whi[0][kt]);
            mma_bf16(cxa[mt][1], ah, whi[1][kt]);
            mma_bf16(cxa[mt][0], ah, wlo[0][kt]);
            mma_bf16(cxa[mt][1], ah, wlo[1][kt]);
            mma_bf16(cxa[mt][0], al, whi[0][kt]);
            mma_bf16(cxa[mt][1], al, whi[1][kt]);
        }
    }

    const int col0 = 16 * w + 2 * tig;

    for (int t = 0; t < T_LEN; t++) {
        // ======== PHASE 1: h-GEMM(t) (kt 4..7) into cxa, store pre ========
#pragma unroll
        for (int mt = 0; mt < 3; mt++) if (mt < mc) {
            uint32_t bHi = (uint32_t)__cvta_generic_to_shared(
                sm + SH_BASE + 0 * SX_PLANE + (mt * 16 + arow) * XPITCH + acol);
            uint32_t bLo = (uint32_t)__cvta_generic_to_shared(
                sm + SH_BASE + 1 * SX_PLANE + (mt * 16 + arow) * XPITCH + acol);
#pragma unroll
            for (int kt = 4; kt < 8; kt++) {
                uint32_t ah[4], al[4];
                ldsm4(ah, bHi + (kt - 4) * 32);
                ldsm4(al, bLo + (kt - 4) * 32);
                mma_bf16(cxa[mt][0], ah, whi[0][kt]);
                mma_bf16(cxa[mt][1], ah, whi[1][kt]);
                mma_bf16(cxa[mt][0], ah, wlo[0][kt]);
                mma_bf16(cxa[mt][1], ah, wlo[1][kt]);
                mma_bf16(cxa[mt][0], al, whi[0][kt]);
                mma_bf16(cxa[mt][1], al, whi[1][kt]);
            }
            *(float2*)&sPre[(mt * 16 + g) * PPITCH + col0] =
                make_float2(cxa[mt][0][0], cxa[mt][0][1]);
            *(float2*)&sPre[(mt * 16 + g + 8) * PPITCH + col0] =
                make_float2(cxa[mt][0][2], cxa[mt][0][3]);
            *(float2*)&sPre[(mt * 16 + g) * PPITCH + col0 + 8] =
                make_float2(cxa[mt][1][0], cxa[mt][1][1]);
            *(float2*)&sPre[(mt * 16 + g + 8) * PPITCH + col0 + 8] =
                make_float2(cxa[mt][1][2], cxa[mt][1][3]);
        }
        // finalize gate for x(t+2) (probe was issued last step; spin if short)
        if (has_src && j == 0 && t + 2 < T_LEN) {
            int v = avail_c;
            while (v < t + 2) { v = acq_load(src_flag); if (v < t + 2) __nanosleep(40); }
            avail_c = v;
        }
        cp_wait0();
        __syncthreads();   // MID: pre visible, x(t+1) landed
        if (!is_last && j == 0 && t >= 2 && !(t & 1)) publish(my_flag, t - 1);

        // ======== PHASE 2: prefetch x(t+2) + cell(t) + x-GEMM(t+1) ========
        if (t + 2 < T_LEN) {
            int xb_cur = t & 1;   // buffer that held x(t), now free
#pragma unroll
            for (int q = 0; q < 2; q++) {
                int c = q * 512 + j;
                if (c < nchunk) {
                    int r = c >> 4, sub = c & 15, hl = sub >> 3, ch = sub & 7;
                    cp_async16(sm + (2 * xb_cur + hl) * SX_PLANE + r * XPITCH + ch * 8,
                               &g_seq[in_sel][hl][((size_t)(t + 2) * NB + mstart + r) * 32 + ch * 4]);
                }
            }
        }
        cp_commit();

        // cell(t)
#pragma unroll
        for (int q = 0; q < 3; q++) if (q < mc) {
            int p = q * 512 + j, ml = p >> 5, np = p & 31;
            float2 pi2 = *(const float2*)&sPre[ml * PPITCH + 2 * np];
            float2 pf2 = *(const float2*)&sPre[ml * PPITCH + 64 + 2 * np];
            float2 pg2 = *(const float2*)&sPre[ml * PPITCH + 128 + 2 * np];
            float2 po2 = *(const float2*)&sPre[ml * PPITCH + 192 + 2 * np];
            float pi_[2] = {pi2.x, pi2.y}, pf_[2] = {pf2.x, pf2.y};
            float pg_[2] = {pg2.x, pg2.y}, po_[2] = {po2.x, po2.y};
#pragma unroll
            for (int i = 0; i < 2; i++) {
                float it = sigf(pi_[i]), ft = sigf(pf_[i]);
                float gt = tanh_f(pg_[i]), ot = sigf(po_[i]);
                float cn = ft * cst[2 * q + i] + it * gt;
                float hn = ot * tanh_f(cn);
                if (t < lenq[q]) { cst[2 * q + i] = cn; hst[2 * q + i] = hn; }
            }
            uint32_t lp, hp = bfsplit2(hst[2 * q], hst[2 * q + 1], &lp);
            *(uint32_t*)(sm + SH_BASE + 0 * SX_PLANE + ml * XPITCH + 2 * np) = hp;
            *(uint32_t*)(sm + SH_BASE + 1 * SX_PLANE + ml * XPITCH + 2 * np) = lp;
            if (!is_last) {
                size_t o = ((size_t)t * NB + mstart + ml) * 32 + np;
                g_seq[out_sel][0][o] = hp;
                g_seq[out_sel][1][o] = lp;
            }
        }

        // x-GEMM(t+1) (kt 0..3) into fresh cxa
        if (t + 1 < T_LEN) {
            int xb_nxt = (t + 1) & 1;
#pragma unroll
            for (int mt = 0; mt < 3; mt++) if (mt < mc) {
#pragma unroll
                for (int nt = 0; nt < 2; nt++) {
                    cxa[mt][nt][0] = be[nt]; cxa[mt][nt][1] = bo_[nt];
                    cxa[mt][nt][2] = be[nt]; cxa[mt][nt][3] = bo_[nt];
                }
                uint32_t bHi = (uint32_t)__cvta_generic_to_shared(
                    sm + (2 * xb_nxt + 0) * SX_PLANE + (mt * 16 + arow) * XPITCH + acol);
                uint32_t bLo = (uint32_t)__cvta_generic_to_shared(
                    sm + (2 * xb_nxt + 1) * SX_PLANE + (mt * 16 + arow) * XPITCH + acol);
#pragma unroll
                for (int kt = 0; kt < 4; kt++) {
                    uint32_t ah[4], al[4];
                    ldsm4(ah, bHi + kt * 32);
                    ldsm4(al, bLo + kt * 32);
                    mma_bf16(cxa[mt][0], ah, whi[0][kt]);
                    mma_bf16(cxa[mt][1], ah, whi[1][kt]);
                    mma_bf16(cxa[mt][0], ah, wlo[0][kt]);
                    mma_bf16(cxa[mt][1], ah, wlo[1][kt]);
                    mma_bf16(cxa[mt][0], al, whi[0][kt]);
                    mma_bf16(cxa[mt][1], al, whi[1][kt]);
                }
            }
        }

        if (!is_last && (t & 1)) __threadfence();
        // early probe for the next gate (latency hidden by next phase1)
        if (has_src && j == 0 && t + 3 < T_LEN && avail_c < t + 3)
            avail_c = acq_load(src_flag);
        __syncthreads();   // BOTTOM: h(t) visible for phase1(t+1)
    }
    if (!is_last && j == 0) publish(my_flag, T_LEN - 1);

    // ---- head on last layer ----
    if (is_last) {
#pragma unroll
        for (int q = 0; q < 3; q++) if (q < mc) {
            int p = q * 512 + j, ml = p >> 5, np = p & 31;
            sPre[ml * HID + 2 * np]     = hst[2 * q];
            sPre[ml * HID + 2 * np + 1] = hst[2 * q + 1];
        }
        __syncthreads();
        if (j < rows) {
            float s = 0.f;
#pragma unroll
            for (int k = 0; k < HID; k++) s += sPre[j * HID + k] * head_w[k];
            logits[mstart + j] = s + head_b[0];
        }
    }
}

extern "C" void kernel_launch(void* const* d_in, const int* in_sizes, int n_in,
                              void* d_out, int out_size) {
    const int*   x       = (const int*)d_in[0];
    const int*   lengths = (const int*)d_in[1];
    const float* emb     = (const float*)d_in[2];
    const float* Wi      = (const float*)d_in[3];
    const float* Wf      = (const float*)d_in[4];
    const float* Wg      = (const float*)d_in[5];
    const float* Wo      = (const float*)d_in[6];
    const float* bi      = (const float*)d_in[7];
    const float* bf      = (const float*)d_in[8];
    const float* bg      = (const float*)d_in[9];
    const float* bo      = (const float*)d_in[10];
    const float* init_h  = (const float*)d_in[11];
    const float* head_w  = (const float*)d_in[12];
    const float* head_b  = (const float*)d_in[13];
    float* logits = (float*)d_out;

    cudaFuncSetAttribute(lstm_fused, cudaFuncAttributeMaxDynamicSharedMemorySize,
                         SMEM_BYTES);

    gather_emb<<<(size_t)T_LEN * NB * 32 / 256, 256>>>(x, emb);
    lstm_fused<<<NLAY * NCTA_L, 512, SMEM_BYTES>>>(
        Wi, Wf, Wg, Wo, bi, bf, bg, bo,
        init_h, lengths, head_w, head_b, logits);
}

// round 5
// speedup vs baseline: 2.7415x; 1.0005x over previous
#include <cuda_runtime.h>
#include <cuda_bf16.h>
#include <cstdint>

#define T_LEN 1024
#define NB    1024
#define HID   64
#define NLAY  5
#define NCTA_L 29          // CTAs per layer (one wave: 5*29=145 <= 148)
#define N3    6            // first 6 CTAs: 48 rows (3 mtiles); other 23: 32 rows
#define XPITCH 72          // halfwords per x/h row plane (144B, odd 16B multiple)
#define PPITCH 264         // floats per pre-activation row
#define SX_PLANE (48 * XPITCH)                    // 3456 halfwords
#define SH_BASE  (4 * SX_PLANE)                   // after 2 bufs x 2 (hi/lo) x-planes
#define SPRE_OFF ((SH_BASE + 2 * SX_PLANE) * 2)   // byte offset of sPre
#define SMEM_BYTES (SPRE_OFF + 48 * PPITCH * 4)   // 92160

// Inter-layer activation sequences, bf16 hi/lo pairs packed 2-per-u32.
__device__ uint32_t g_seq[2][2][(size_t)T_LEN * NB * (HID / 2)];
__device__ int g_prog[NLAY * NCTA_L];

// ---------------- helpers ----------------
static __device__ __forceinline__ uint16_t bfbits(__nv_bfloat16 h) {
    return __bfloat16_as_ushort(h);
}
static __device__ __forceinline__ uint32_t bfsplit2(float a, float b, uint32_t* lo) {
    __nv_bfloat16 ha = __float2bfloat16(a), hb = __float2bfloat16(b);
    float ra = a - __bfloat162float(ha);
    float rb = b - __bfloat162float(hb);
    __nv_bfloat16 la = __float2bfloat16(ra), lb = __float2bfloat16(rb);
    *lo = ((uint32_t)bfbits(lb) << 16) | bfbits(la);
    return ((uint32_t)bfbits(hb) << 16) | bfbits(ha);
}
static __device__ __forceinline__ void ldsm4(uint32_t a[4], uint32_t addr) {
    asm volatile("ldmatrix.sync.aligned.m8n8.x4.shared.b16 {%0,%1,%2,%3}, [%4];"
                 : "=r"(a[0]), "=r"(a[1]), "=r"(a[2]), "=r"(a[3]) : "r"(addr));
}
static __device__ __forceinline__ void mma_bf16(float c[4], const uint32_t a[4],
                                                const uint32_t b[2]) {
    asm volatile(
        "mma.sync.aligned.m16n8k16.row.col.f32.bf16.bf16.f32 "
        "{%0,%1,%2,%3}, {%4,%5,%6,%7}, {%8,%9}, {%0,%1,%2,%3};"
        : "+f"(c[0]), "+f"(c[1]), "+f"(c[2]), "+f"(c[3])
        : "r"(a[0]), "r"(a[1]), "r"(a[2]), "r"(a[3]), "r"(b[0]), "r"(b[1]));
}
static __device__ __forceinline__ void cp_async16(void* sdst, const void* gsrc) {
    unsigned sa = (unsigned)__cvta_generic_to_shared(sdst);
    asm volatile("cp.async.cg.shared.global [%0], [%1], 16;\n" :: "r"(sa), "l"(gsrc));
}
static __device__ __forceinline__ void cp_commit() {
    asm volatile("cp.async.commit_group;\n" ::: "memory");
}
static __device__ __forceinline__ void cp_wait0() {
    asm volatile("cp.async.wait_group 0;\n" ::: "memory");
}
static __device__ __forceinline__ float sigf(float x) {
    float e = __expf(-x);
    return __fdividef(1.f, 1.f + e);
}
static __device__ __forceinline__ float tanh_f(float x) {
    x = fminf(fmaxf(x, -15.f), 15.f);
    float e = __expf(-2.f * x);
    return __fdividef(1.f - e, 1.f + e);
}
static __device__ __forceinline__ void publish(int* p, int v) {
    asm volatile("st.release.gpu.global.b32 [%0], %1;" :: "l"(p), "r"(v) : "memory");
}
static __device__ __forceinline__ int acq_load(const int* p) {
    int v;
    asm volatile("ld.acquire.gpu.global.b32 %0, [%1];" : "=r"(v) : "l"(p) : "memory");
    return v;
}

// ---------------- embedding gather -> g_seq[0] (+ flag reset) ----------------
__global__ void gather_emb(const int* __restrict__ x, const float* __restrict__ emb) {
    if (blockIdx.x == 0 && threadIdx.x < NLAY * NCTA_L) g_prog[threadIdx.x] = -1;
    size_t e = (size_t)blockIdx.x * 256 + threadIdx.x;   // over T*B*32
    int h2 = e & 31;
    int b  = (e >> 5) & (NB - 1);
    int t  = (int)(e >> 15);
    int xi = x[(size_t)b * T_LEN + t];
    float2 v = ((const float2*)(emb + (size_t)xi * HID))[h2];
    uint32_t lp, hp = bfsplit2(v.x, v.y, &lp);
    size_t o = ((size_t)t * NB + b) * (HID / 2) + h2;
    g_seq[0][0][o] = hp;
    g_seq[0][1][o] = lp;
}

// ---------------- fused one-wave pipelined LSTM ----------------
__global__ void __launch_bounds__(512, 1) lstm_fused(
    const float* __restrict__ Wi, const float* __restrict__ Wf,
    const float* __restrict__ Wg, const float* __restrict__ Wo,
    const float* __restrict__ bi, const float* __restrict__ bf,
    const float* __restrict__ bg, const float* __restrict__ bo,
    const float* __restrict__ init_h, const int* __restrict__ lengths,
    const float* __restrict__ head_w, const float* __restrict__ head_b,
    float* __restrict__ logits)
{
    extern __shared__ __align__(16) uint16_t sm[];
    float* sPre = (float*)((char*)sm + SPRE_OFF);

    const int layer = blockIdx.x / NCTA_L;
    const int gi    = blockIdx.x - layer * NCTA_L;
    const int mc     = (gi < N3) ? 3 : 2;              // mtiles in this CTA
    const int mstart = (gi < N3) ? 48 * gi : 288 + 32 * (gi - N3);
    const int rows   = 16 * mc;
    const int nchunk = 256 * mc;                        // 16B cp.async chunks per buf
    const int in_sel  = layer & 1;
    const int out_sel = in_sel ^ 1;
    const int is_last = (layer == NLAY - 1);
    const int has_src = (layer > 0);

    const int j    = threadIdx.x;
    const int lane = j & 31;
    const int w    = j >> 5;
    const int g    = lane >> 2;
    const int tig  = lane & 3;
    const int arow = lane & 15;
    const int acol = (lane >> 4) * 8;

    int* my_flag        = &g_prog[layer * NCTA_L + gi];
    const int* src_flag = &g_prog[(layer - 1) * NCTA_L + gi];
    int avail_c = -1;

    // ---- weight B-fragments (hi/lo) in registers, biases ----
    uint32_t whi[2][8][2], wlo[2][8][2];
    float be[2], bo_[2];
#pragma unroll
    for (int nt = 0; nt < 2; nt++) {
        int jo   = 16 * w + 8 * nt + g;
        int gate = jo >> 6, nc = jo & 63;
        const float* Wr =
            (gate == 0 ? Wi : gate == 1 ? Wf : gate == 2 ? Wg : Wo) +
            (size_t)(layer * HID + nc) * 128;
#pragma unroll
        for (int kt = 0; kt < 8; kt++) {
            int k0 = 16 * kt + 2 * tig;
            whi[nt][kt][0] = bfsplit2(Wr[k0],     Wr[k0 + 1], &wlo[nt][kt][0]);
            whi[nt][kt][1] = bfsplit2(Wr[k0 + 8], Wr[k0 + 9], &wlo[nt][kt][1]);
        }
        int je = 16 * w + 8 * nt + 2 * tig;
        int ge = je >> 6, ne = je & 63;
        be[nt] = (ge == 0 ? bi : ge == 1 ? bf : ge == 2 ? bg : bo)[layer * HID + ne];
        int jo2 = je + 1;
        int go2 = jo2 >> 6, no2 = jo2 & 63;
        bo_[nt] = (go2 == 0 ? bi : go2 == 1 ? bf : go2 == 2 ? bg : bo)[layer * HID + no2];
    }

    // ---- cell state: thread owns pairs p = q*512+j, q<mc (m=p>>5, np=p&31) ----
    float hst[6], cst[6];
    int lenq[3];
#pragma unroll
    for (int q = 0; q < 3; q++) if (q < mc) {
        int p = q * 512 + j, ml = p >> 5, np = p & 31;
        lenq[q] = lengths[mstart + ml];
        hst[2 * q]     = tanh_f(init_h[layer * HID + 2 * np]);
        hst[2 * q + 1] = tanh_f(init_h[layer * HID + 2 * np + 1]);
        cst[2 * q] = 0.f; cst[2 * q + 1] = 0.f;
    }

    // gate x(0),x(1) for layers > 0
    if (has_src && j == 0) {
        int v = -1;
        while (v < 1) { v = acq_load(src_flag); if (v < 1) __nanosleep(60); }
        avail_c = v;
    }
    __syncthreads();

    // prefetch x(0) into sX buf0
#pragma unroll
    for (int q = 0; q < 2; q++) {
        int c = q * 512 + j;
        if (c < nchunk) {
            int r = c >> 4, sub = c & 15, hl = sub >> 3, ch = sub & 7;
            cp_async16(sm + hl * SX_PLANE + r * XPITCH + ch * 8,
                       &g_seq[in_sel][hl][((size_t)0 * NB + mstart + r) * 32 + ch * 4]);
        }
    }
    cp_commit();

    // h0 into sH
#pragma unroll
    for (int q = 0; q < 3; q++) if (q < mc) {
        int p = q * 512 + j, ml = p >> 5, np = p & 31;
        uint32_t lp, hp = bfsplit2(hst[2 * q], hst[2 * q + 1], &lp);
        *(uint32_t*)(sm + SH_BASE + 0 * SX_PLANE + ml * XPITCH + 2 * np) = hp;
        *(uint32_t*)(sm + SH_BASE + 1 * SX_PLANE + ml * XPITCH + 2 * np) = lp;
    }
    cp_wait0();
    __syncthreads();

    // prologue: prefetch x(1) into buf1, then x-GEMM(0) into cxa
#pragma unroll
    for (int q = 0; q < 2; q++) {
        int c = q * 512 + j;
        if (c < nchunk) {
            int r = c >> 4, sub = c & 15, hl = sub >> 3, ch = sub & 7;
            cp_async16(sm + (2 + hl) * SX_PLANE + r * XPITCH + ch * 8,
                       &g_seq[in_sel][hl][((size_t)1 * NB + mstart + r) * 32 + ch * 4]);
        }
    }
    cp_commit();

    float cxa[3][2][4];
#pragma unroll
    for (int mt = 0; mt < 3; mt++) if (mt < mc) {
#pragma unroll
        for (int nt = 0; nt < 2; nt++) {
            cxa[mt][nt][0] = be[nt]; cxa[mt][nt][1] = bo_[nt];
            cxa[mt][nt][2] = be[nt]; cxa[mt][nt][3] = bo_[nt];
        }
        uint32_t bHi = (uint32_t)__cvta_generic_to_shared(
            sm + 0 * SX_PLANE + (mt * 16 + arow) * XPITCH + acol);
        uint32_t bLo = (uint32_t)__cvta_generic_to_shared(
            sm + 1 * SX_PLANE + (mt * 16 + arow) * XPITCH + acol);
#pragma unroll
        for (int kt = 0; kt < 4; kt++) {
            uint32_t ah[4], al[4];
            ldsm4(ah, bHi + kt * 32);
            ldsm4(al, bLo + kt * 32);
            mma_bf16(cxa[mt][0], ah, whi[0][kt]);
            mma_bf16(cxa[mt][1], ah, whi[1][kt]);
            mma_bf16(cxa[mt][0], ah, wlo[0][kt]);
            mma_bf16(cxa[mt][1], ah, wlo[1][kt]);
            mma_bf16(cxa[mt][0], al, whi[0][kt]);
            mma_bf16(cxa[mt][1], al, whi[1][kt]);
        }
    }

    const int col0 = 16 * w + 2 * tig;

    for (int t = 0; t < T_LEN; t++) {
        // ======== PHASE 1: h-GEMM(t) (kt 4..7) into cxa, store pre ========
#pragma unroll
        for (int mt = 0; mt < 3; mt++) if (mt < mc) {
            uint32_t bHi = (uint32_t)__cvta_generic_to_shared(
                sm + SH_BASE + 0 * SX_PLANE + (mt * 16 + arow) * XPITCH + acol);
            uint32_t bLo = (uint32_t)__cvta_generic_to_shared(
                sm + SH_BASE + 1 * SX_PLANE + (mt * 16 + arow) * XPITCH + acol);
#pragma unroll
            for (int kt = 4; kt < 8; kt++) {
                uint32_t ah[4], al[4];
                ldsm4(ah, bHi + (kt - 4) * 32);
                ldsm4(al, bLo + (kt - 4) * 32);
                mma_bf16(cxa[mt][0], ah, whi[0][kt]);
                mma_bf16(cxa[mt][1], ah, whi[1][kt]);
                mma_bf16(cxa[mt][0], ah, wlo[0][kt]);
                mma_bf16(cxa[mt][1], ah, wlo[1][kt]);
                mma_bf16(cxa[mt][0], al, whi[0][kt]);
                mma_bf16(cxa[mt][1], al, whi[1][kt]);
            }
            *(float2*)&sPre[(mt * 16 + g) * PPITCH + col0] =
                make_float2(cxa[mt][0][0], cxa[mt][0][1]);
            *(float2*)&sPre[(mt * 16 + g + 8) * PPITCH + col0] =
                make_float2(cxa[mt][0][2], cxa[mt][0][3]);
            *(float2*)&sPre[(mt * 16 + g) * PPITCH + col0 + 8] =
                make_float2(cxa[mt][1][0], cxa[mt][1][1]);
            *(float2*)&sPre[(mt * 16 + g + 8) * PPITCH + col0 + 8] =
                make_float2(cxa[mt][1][2], cxa[mt][1][3]);
        }
        // finalize gate for x(t+2) (probe was issued last step; spin if short)
        if (has_src && j == 0 && t + 2 < T_LEN) {
            int v = avail_c;
            while (v < t + 2) { v = acq_load(src_flag); if (v < t + 2) __nanosleep(40); }
            avail_c = v;
        }
        cp_wait0();
        __syncthreads();   // MID: pre visible, x(t+1) landed
        if (!is_last && j == 0 && t >= 2 && !(t & 1)) publish(my_flag, t - 1);

        // ======== PHASE 2: prefetch x(t+2) + cell(t) + x-GEMM(t+1) ========
        if (t + 2 < T_LEN) {
            int xb_cur = t & 1;   // buffer that held x(t), now free
#pragma unroll
            for (int q = 0; q < 2; q++) {
                int c = q * 512 + j;
                if (c < nchunk) {
                    int r = c >> 4, sub = c & 15, hl = sub >> 3, ch = sub & 7;
                    cp_async16(sm + (2 * xb_cur + hl) * SX_PLANE + r * XPITCH + ch * 8,
                               &g_seq[in_sel][hl][((size_t)(t + 2) * NB + mstart + r) * 32 + ch * 4]);
                }
            }
        }
        cp_commit();

        // cell(t)
#pragma unroll
        for (int q = 0; q < 3; q++) if (q < mc) {
            int p = q * 512 + j, ml = p >> 5, np = p & 31;
            float2 pi2 = *(const float2*)&sPre[ml * PPITCH + 2 * np];
            float2 pf2 = *(const float2*)&sPre[ml * PPITCH + 64 + 2 * np];
            float2 pg2 = *(const float2*)&sPre[ml * PPITCH + 128 + 2 * np];
            float2 po2 = *(const float2*)&sPre[ml * PPITCH + 192 + 2 * np];
            float pi_[2] = {pi2.x, pi2.y}, pf_[2] = {pf2.x, pf2.y};
            float pg_[2] = {pg2.x, pg2.y}, po_[2] = {po2.x, po2.y};
#pragma unroll
            for (int i = 0; i < 2; i++) {
                float it = sigf(pi_[i]), ft = sigf(pf_[i]);
                float gt = tanh_f(pg_[i]), ot = sigf(po_[i]);
                float cn = ft * cst[2 * q + i] + it * gt;
                float hn = ot * tanh_f(cn);
                if (t < lenq[q]) { cst[2 * q + i] = cn; hst[2 * q + i] = hn; }
            }
            uint32_t lp, hp = bfsplit2(hst[2 * q], hst[2 * q + 1], &lp);
            *(uint32_t*)(sm + SH_BASE + 0 * SX_PLANE + ml * XPITCH + 2 * np) = hp;
            *(uint32_t*)(sm + SH_BASE + 1 * SX_PLANE + ml * XPITCH + 2 * np) = lp;
            if (!is_last) {
                size_t o = ((size_t)t * NB + mstart + ml) * 32 + np;
                g_seq[out_sel][0][o] = hp;
                g_seq[out_sel][1][o] = lp;
            }
        }

        // x-GEMM(t+1) (kt 0..3) into fresh cxa
        if (t + 1 < T_LEN) {
            int xb_nxt = (t + 1) & 1;
#pragma unroll
            for (int mt = 0; mt < 3; mt++) if (mt < mc) {
#pragma unroll
                for (int nt = 0; nt < 2; nt++) {
                    cxa[mt][nt][0] = be[nt]; cxa[mt][nt][1] = bo_[nt];
                    cxa[mt][nt][2] = be[nt]; cxa[mt][nt][3] = bo_[nt];
                }
                uint32_t bHi = (uint32_t)__cvta_generic_to_shared(
                    sm + (2 * xb_nxt + 0) * SX_PLANE + (mt * 16 + arow) * XPITCH + acol);
                uint32_t bLo = (uint32_t)__cvta_generic_to_shared(
                    sm + (2 * xb_nxt + 1) * SX_PLANE + (mt * 16 + arow) * XPITCH + acol);
#pragma unroll
                for (int kt = 0; kt < 4; kt++) {
                    uint32_t ah[4], al[4];
                    ldsm4(ah, bHi + kt * 32);
                    ldsm4(al, bLo + kt * 32);
                    mma_bf16(cxa[mt][0], ah, whi[0][kt]);
                    mma_bf16(cxa[mt][1], ah, whi[1][kt]);
                    mma_bf16(cxa[mt][0], ah, wlo[0][kt]);
                    mma_bf16(cxa[mt][1], ah, wlo[1][kt]);
                    mma_bf16(cxa[mt][0], al, whi[0][kt]);
                    mma_bf16(cxa[mt][1], al, whi[1][kt]);
                }
            }
        }

        if (!is_last && (t & 1)) __threadfence();
        // early probe for the next gate (latency hidden by next phase1)
        if (has_src && j == 0 && t + 3 < T_LEN && avail_c < t + 3)
            avail_c = acq_load(src_flag);
        __syncthreads();   // BOTTOM: h(t) visible for phase1(t+1)
    }
    if (!is_last && j == 0) publish(my_flag, T_LEN - 1);

    // ---- head on last layer ----
    if (is_last) {
#pragma unroll
        for (int q = 0; q < 3; q++) if (q < mc) {
            int p = q * 512 + j, ml = p >> 5, np = p & 31;
            sPre[ml * HID + 2 * np]     = hst[2 * q];
            sPre[ml * HID + 2 * np + 1] = hst[2 * q + 1];
        }
        __syncthreads();
        if (j < rows) {
            float s = 0.f;
#pragma unroll
            for (int k = 0; k < HID; k++) s += sPre[j * HID + k] * head_w[k];
            logits[mstart + j] = s + head_b[0];
        }
    }
}

extern "C" void kernel_launch(void* const* d_in, const int* in_sizes, int n_in,
                              void* d_out, int out_size) {
    const int*   x       = (const int*)d_in[0];
    const int*   lengths = (const int*)d_in[1];
    const float* emb     = (const float*)d_in[2];
    const float* Wi      = (const float*)d_in[3];
    const float* Wf      = (const float*)d_in[4];
    const float* Wg      = (const float*)d_in[5];
    const float* Wo      = (const float*)d_in[6];
    const float* bi      = (const float*)d_in[7];
    const float* bf      = (const float*)d_in[8];
    const float* bg      = (const float*)d_in[9];
    const float* bo      = (const float*)d_in[10];
    const float* init_h  = (const float*)d_in[11];
    const float* head_w  = (const float*)d_in[12];
    const float* head_b  = (const float*)d_in[13];
    float* logits = (float*)d_out;

    cudaFuncSetAttribute(lstm_fused, cudaFuncAttributeMaxDynamicSharedMemorySize,
                         SMEM_BYTES);

    gather_emb<<<(size_t)T_LEN * NB * 32 / 256, 256>>>(x, emb);
    lstm_fused<<<NLAY * NCTA_L, 512, SMEM_BYTES>>>(
        Wi, Wf, Wg, Wo, bi, bf, bg, bo,
        init_h, lengths, head_w, head_b, logits);
}

// round 6
// speedup vs baseline: 2.7566x; 1.0055x over previous
#include <cuda_runtime.h>
#include <cuda_bf16.h>
#include <cstdint>

#define T_LEN 1024
#define NB    1024
#define HID   64
#define NLAY  5
#define NCTA_L 29          // CTAs per layer (one wave: 5*29=145 <= 148)
#define N3    6            // first 6 CTAs: 48 rows (3 mtiles); other 23: 32 rows
#define XPITCH 72          // halfwords per x/h row plane (144B, odd 16B multiple)
#define PPITCH 264         // floats per pre-activation row
#define SX_PLANE (48 * XPITCH)            // 3456 halfwords per plane
#define XBUF_STRIDE (2 * SX_PLANE)        // hi+lo planes per x buffer
#define SH_BASE  (4 * XBUF_STRIDE)        // after 4 x-buffers
#define SPRE_OFF ((SH_BASE + 2 * SX_PLANE) * 2)   // byte offset of sPre
#define SMEM_BYTES (SPRE_OFF + 48 * PPITCH * 4)   // 119808 bytes

// Inter-layer activation sequences, bf16 hi/lo pairs packed 2-per-u32.
__device__ uint32_t g_seq[2][2][(size_t)T_LEN * NB * (HID / 2)];
__device__ int g_prog[NLAY * NCTA_L];

// ---------------- helpers ----------------
static __device__ __forceinline__ uint16_t bfbits(__nv_bfloat16 h) {
    return __bfloat16_as_ushort(h);
}
static __device__ __forceinline__ uint32_t bfsplit2(float a, float b, uint32_t* lo) {
    __nv_bfloat16 ha = __float2bfloat16(a), hb = __float2bfloat16(b);
    float ra = a - __bfloat162float(ha);
    float rb = b - __bfloat162float(hb);
    __nv_bfloat16 la = __float2bfloat16(ra), lb = __float2bfloat16(rb);
    *lo = ((uint32_t)bfbits(lb) << 16) | bfbits(la);
    return ((uint32_t)bfbits(hb) << 16) | bfbits(ha);
}
static __device__ __forceinline__ void ldsm4(uint32_t a[4], uint32_t addr) {
    asm volatile("ldmatrix.sync.aligned.m8n8.x4.shared.b16 {%0,%1,%2,%3}, [%4];"
                 : "=r"(a[0]), "=r"(a[1]), "=r"(a[2]), "=r"(a[3]) : "r"(addr));
}
static __device__ __forceinline__ void mma_bf16(float c[4], const uint32_t a[4],
                                                const uint32_t b[2]) {
    asm volatile(
        "mma.sync.aligned.m16n8k16.row.col.f32.bf16.bf16.f32 "
        "{%0,%1,%2,%3}, {%4,%5,%6,%7}, {%8,%9}, {%0,%1,%2,%3};"
        : "+f"(c[0]), "+f"(c[1]), "+f"(c[2]), "+f"(c[3])
        : "r"(a[0]), "r"(a[1]), "r"(a[2]), "r"(a[3]), "r"(b[0]), "r"(b[1]));
}
static __device__ __forceinline__ void cp_async16(void* sdst, const void* gsrc) {
    unsigned sa = (unsigned)__cvta_generic_to_shared(sdst);
    asm volatile("cp.async.cg.shared.global [%0], [%1], 16;\n" :: "r"(sa), "l"(gsrc));
}
static __device__ __forceinline__ void cp_commit() {
    asm volatile("cp.async.commit_group;\n" ::: "memory");
}
static __device__ __forceinline__ void cp_wait3() {
    asm volatile("cp.async.wait_group 3;\n" ::: "memory");
}
static __device__ __forceinline__ float sigf(float x) {
    float e = __expf(-x);
    return __fdividef(1.f, 1.f + e);
}
static __device__ __forceinline__ float tanh_f(float x) {
    x = fminf(fmaxf(x, -15.f), 15.f);
    float e = __expf(-2.f * x);
    return __fdividef(1.f - e, 1.f + e);
}
static __device__ __forceinline__ void publish(int* p, int v) {
    asm volatile("st.release.gpu.global.b32 [%0], %1;" :: "l"(p), "r"(v) : "memory");
}
static __device__ __forceinline__ int acq_load(const int* p) {
    int v;
    asm volatile("ld.acquire.gpu.global.b32 %0, [%1];" : "=r"(v) : "l"(p) : "memory");
    return v;
}

// ---------------- embedding gather -> g_seq[0] (+ flag reset) ----------------
__global__ void gather_emb(const int* __restrict__ x, const float* __restrict__ emb) {
    if (blockIdx.x == 0 && threadIdx.x < NLAY * NCTA_L) g_prog[threadIdx.x] = -1;
    size_t e = (size_t)blockIdx.x * 256 + threadIdx.x;   // over T*B*32
    int h2 = e & 31;
    int b  = (e >> 5) & (NB - 1);
    int t  = (int)(e >> 15);
    int xi = x[(size_t)b * T_LEN + t];
    float2 v = ((const float2*)(emb + (size_t)xi * HID))[h2];
    uint32_t lp, hp = bfsplit2(v.x, v.y, &lp);
    size_t o = ((size_t)t * NB + b) * (HID / 2) + h2;
    g_seq[0][0][o] = hp;
    g_seq[0][1][o] = lp;
}

// ---------------- fused one-wave pipelined LSTM ----------------
__global__ void __launch_bounds__(512, 1) lstm_fused(
    const float* __restrict__ Wi, const float* __restrict__ Wf,
    const float* __restrict__ Wg, const float* __restrict__ Wo,
    const float* __restrict__ bi, const float* __restrict__ bf,
    const float* __restrict__ bg, const float* __restrict__ bo,
    const float* __restrict__ init_h, const int* __restrict__ lengths,
    const float* __restrict__ head_w, const float* __restrict__ head_b,
    float* __restrict__ logits)
{
    extern __shared__ __align__(16) uint16_t sm[];
    float* sPre = (float*)((char*)sm + SPRE_OFF);

    const int layer = blockIdx.x / NCTA_L;
    const int gi    = blockIdx.x - layer * NCTA_L;
    const int mc     = (gi < N3) ? 3 : 2;              // mtiles in this CTA
    const int mstart = (gi < N3) ? 48 * gi : 288 + 32 * (gi - N3);
    const int rows   = 16 * mc;
    const int nchunk = 256 * mc;                        // 16B cp.async chunks per buf
    const int in_sel  = layer & 1;
    const int out_sel = in_sel ^ 1;
    const int is_last = (layer == NLAY - 1);
    const int has_src = (layer > 0);

    const int j    = threadIdx.x;
    const int lane = j & 31;
    const int w    = j >> 5;
    const int g    = lane >> 2;
    const int tig  = lane & 3;
    const int arow = lane & 15;
    const int acol = (lane >> 4) * 8;

    int* my_flag        = &g_prog[layer * NCTA_L + gi];
    const int* src_flag = &g_prog[(layer - 1) * NCTA_L + gi];
    int avail_c = -1;

    // ---- weight B-fragments (hi/lo) in registers, biases ----
    uint32_t whi[2][8][2], wlo[2][8][2];
    float be[2], bo_[2];
#pragma unroll
    for (int nt = 0; nt < 2; nt++) {
        int jo   = 16 * w + 8 * nt + g;
        int gate = jo >> 6, nc = jo & 63;
        const float* Wr =
            (gate == 0 ? Wi : gate == 1 ? Wf : gate == 2 ? Wg : Wo) +
            (size_t)(layer * HID + nc) * 128;
#pragma unroll
        for (int kt = 0; kt < 8; kt++) {
            int k0 = 16 * kt + 2 * tig;
            whi[nt][kt][0] = bfsplit2(Wr[k0],     Wr[k0 + 1], &wlo[nt][kt][0]);
            whi[nt][kt][1] = bfsplit2(Wr[k0 + 8], Wr[k0 + 9], &wlo[nt][kt][1]);
        }
        int je = 16 * w + 8 * nt + 2 * tig;
        int ge = je >> 6, ne = je & 63;
        be[nt] = (ge == 0 ? bi : ge == 1 ? bf : ge == 2 ? bg : bo)[layer * HID + ne];
        int jo2 = je + 1;
        int go2 = jo2 >> 6, no2 = jo2 & 63;
        bo_[nt] = (go2 == 0 ? bi : go2 == 1 ? bf : go2 == 2 ? bg : bo)[layer * HID + no2];
    }

    // ---- cell state: thread owns pairs p = q*512+j, q<mc (m=p>>5, np=p&31) ----
    float hst[6], cst[6];
    int lenq[3];
#pragma unroll
    for (int q = 0; q < 3; q++) if (q < mc) {
        int p = q * 512 + j, ml = p >> 5, np = p & 31;
        lenq[q] = lengths[mstart + ml];
        hst[2 * q]     = tanh_f(init_h[layer * HID + 2 * np]);
        hst[2 * q + 1] = tanh_f(init_h[layer * HID + 2 * np + 1]);
        cst[2 * q] = 0.f; cst[2 * q + 1] = 0.f;
    }

    // prologue gate: wait for producer lead of ~13 steps (covers x(0..12))
    if (has_src && j == 0) {
        int v = -1;
        while (v < 12) { v = acq_load(src_flag); if (v < 12) __nanosleep(40); }
        avail_c = v;
    }
    __syncthreads();

    // prefetch x(0..3) into buffers 0..3, one commit group each
#pragma unroll
    for (int tt = 0; tt < 4; tt++) {
#pragma unroll
        for (int q = 0; q < 2; q++) {
            int c = q * 512 + j;
            if (c < nchunk) {
                int r = c >> 4, sub = c & 15, hl = sub >> 3, ch = sub & 7;
                cp_async16(sm + tt * XBUF_STRIDE + hl * SX_PLANE + r * XPITCH + ch * 8,
                           &g_seq[in_sel][hl][((size_t)tt * NB + mstart + r) * 32 + ch * 4]);
            }
        }
        cp_commit();
    }

    // h0 into sH
#pragma unroll
    for (int q = 0; q < 3; q++) if (q < mc) {
        int p = q * 512 + j, ml = p >> 5, np = p & 31;
        uint32_t lp, hp = bfsplit2(hst[2 * q], hst[2 * q + 1], &lp);
        *(uint32_t*)(sm + SH_BASE + 0 * SX_PLANE + ml * XPITCH + 2 * np) = hp;
        *(uint32_t*)(sm + SH_BASE + 1 * SX_PLANE + ml * XPITCH + 2 * np) = lp;
    }
    cp_wait3();          // x(0) landed (3 groups may remain pending)
    __syncthreads();

    // prologue x-GEMM(0) from buffer 0 into cxa
    float cxa[3][2][4];
#pragma unroll
    for (int mt = 0; mt < 3; mt++) if (mt < mc) {
#pragma unroll
        for (int nt = 0; nt < 2; nt++) {
            cxa[mt][nt][0] = be[nt]; cxa[mt][nt][1] = bo_[nt];
            cxa[mt][nt][2] = be[nt]; cxa[mt][nt][3] = bo_[nt];
        }
        uint32_t bHi = (uint32_t)__cvta_generic_to_shared(
            sm + 0 * SX_PLANE + (mt * 16 + arow) * XPITCH + acol);
        uint32_t bLo = (uint32_t)__cvta_generic_to_shared(
            sm + 1 * SX_PLANE + (mt * 16 + arow) * XPITCH + acol);
#pragma unroll
        for (int kt = 0; kt < 4; kt++) {
            uint32_t ah[4], al[4];
            ldsm4(ah, bHi + kt * 32);
            ldsm4(al, bLo + kt * 32);
            mma_bf16(cxa[mt][0], ah, whi[0][kt]);
            mma_bf16(cxa[mt][1], ah, whi[1][kt]);
            mma_bf16(cxa[mt][0], ah, wlo[0][kt]);
            mma_bf16(cxa[mt][1], ah, wlo[1][kt]);
            mma_bf16(cxa[mt][0], al, whi[0][kt]);
            mma_bf16(cxa[mt][1], al, whi[1][kt]);
        }
    }

    const int col0 = 16 * w + 2 * tig;

    for (int t = 0; t < T_LEN; t++) {
        // ======== PHASE 1: h-GEMM(t) (weights kt 4..7) into cxa, store pre ========
#pragma unroll
        for (int mt = 0; mt < 3; mt++) if (mt < mc) {
            uint32_t bHi = (uint32_t)__cvta_generic_to_shared(
                sm + SH_BASE + 0 * SX_PLANE + (mt * 16 + arow) * XPITCH + acol);
            uint32_t bLo = (uint32_t)__cvta_generic_to_shared(
                sm + SH_BASE + 1 * SX_PLANE + (mt * 16 + arow) * XPITCH + acol);
#pragma unroll
            for (int kt = 4; kt < 8; kt++) {
                uint32_t ah[4], al[4];
                ldsm4(ah, bHi + (kt - 4) * 32);
                ldsm4(al, bLo + (kt - 4) * 32);
                mma_bf16(cxa[mt][0], ah, whi[0][kt]);
                mma_bf16(cxa[mt][1], ah, whi[1][kt]);
                mma_bf16(cxa[mt][0], ah, wlo[0][kt]);
                mma_bf16(cxa[mt][1], ah, wlo[1][kt]);
                mma_bf16(cxa[mt][0], al, whi[0][kt]);
                mma_bf16(cxa[mt][1], al, whi[1][kt]);
            }
            *(float2*)&sPre[(mt * 16 + g) * PPITCH + col0] =
                make_float2(cxa[mt][0][0], cxa[mt][0][1]);
            *(float2*)&sPre[(mt * 16 + g + 8) * PPITCH + col0] =
                make_float2(cxa[mt][0][2], cxa[mt][0][3]);
            *(float2*)&sPre[(mt * 16 + g) * PPITCH + col0 + 8] =
                make_float2(cxa[mt][1][0], cxa[mt][1][1]);
            *(float2*)&sPre[(mt * 16 + g + 8) * PPITCH + col0 + 8] =
                make_float2(cxa[mt][1][2], cxa[mt][1][3]);
        }
        // gate for x(t+4) (cached; load only when short)
        if (has_src && j == 0) {
            int need = t + 4;
            if (need < T_LEN && avail_c < need) {
                int v = acq_load(src_flag);
                while (v < need) { __nanosleep(40); v = acq_load(src_flag); }
                avail_c = v;
            }
        }
        __syncthreads();   // MID: pre visible; acquire ordered before prefetch
        if (!is_last && j == 0 && t >= 1) publish(my_flag, t - 1);

        // ======== PHASE 2: prefetch x(t+4) + cell(t) + x-GEMM(t+1) ========
        if (t + 4 < T_LEN) {
            int b = t & 3;   // == (t+4)&3; buffer consumed at step t-1's x-GEMM(t)
#pragma unroll
            for (int q = 0; q < 2; q++) {
                int c = q * 512 + j;
                if (c < nchunk) {
                    int r = c >> 4, sub = c & 15, hl = sub >> 3, ch = sub & 7;
                    cp_async16(sm + b * XBUF_STRIDE + hl * SX_PLANE + r * XPITCH + ch * 8,
                               &g_seq[in_sel][hl][((size_t)(t + 4) * NB + mstart + r) * 32 + ch * 4]);
                }
            }
        }
        cp_commit();   // unconditional: keeps group numbering aligned

        // cell(t)
#pragma unroll
        for (int q = 0; q < 3; q++) if (q < mc) {
            int p = q * 512 + j, ml = p >> 5, np = p & 31;
            float2 pi2 = *(const float2*)&sPre[ml * PPITCH + 2 * np];
            float2 pf2 = *(const float2*)&sPre[ml * PPITCH + 64 + 2 * np];
            float2 pg2 = *(const float2*)&sPre[ml * PPITCH + 128 + 2 * np];
            float2 po2 = *(const float2*)&sPre[ml * PPITCH + 192 + 2 * np];
            float pi_[2] = {pi2.x, pi2.y}, pf_[2] = {pf2.x, pf2.y};
            float pg_[2] = {pg2.x, pg2.y}, po_[2] = {po2.x, po2.y};
#pragma unroll
            for (int i = 0; i < 2; i++) {
                float it = sigf(pi_[i]), ft = sigf(pf_[i]);
                float gt = tanh_f(pg_[i]), ot = sigf(po_[i]);
                float cn = ft * cst[2 * q + i] + it * gt;
                float hn = ot * tanh_f(cn);
                if (t < lenq[q]) { cst[2 * q + i] = cn; hst[2 * q + i] = hn; }
            }
            uint32_t lp, hp = bfsplit2(hst[2 * q], hst[2 * q + 1], &lp);
            *(uint32_t*)(sm + SH_BASE + 0 * SX_PLANE + ml * XPITCH + 2 * np) = hp;
            *(uint32_t*)(sm + SH_BASE + 1 * SX_PLANE + ml * XPITCH + 2 * np) = lp;
            if (!is_last) {
                size_t o = ((size_t)t * NB + mstart + ml) * 32 + np;
                g_seq[out_sel][0][o] = hp;
                g_seq[out_sel][1][o] = lp;
            }
        }

        cp_wait3();    // x(t+1) guaranteed landed (only 3 newer groups pending)

        // x-GEMM(t+1) (weights kt 0..3) into fresh cxa
        if (t + 1 < T_LEN) {
            int b = (t + 1) & 3;
#pragma unroll
            for (int mt = 0; mt < 3; mt++) if (mt < mc) {
#pragma unroll
                for (int nt = 0; nt < 2; nt++) {
                    cxa[mt][nt][0] = be[nt]; cxa[mt][nt][1] = bo_[nt];
                    cxa[mt][nt][2] = be[nt]; cxa[mt][nt][3] = bo_[nt];
                }
                uint32_t bHi = (uint32_t)__cvta_generic_to_shared(
                    sm + b * XBUF_STRIDE + 0 * SX_PLANE + (mt * 16 + arow) * XPITCH + acol);
                uint32_t bLo = (uint32_t)__cvta_generic_to_shared(
                    sm + b * XBUF_STRIDE + 1 * SX_PLANE + (mt * 16 + arow) * XPITCH + acol);
#pragma unroll
                for (int kt = 0; kt < 4; kt++) {
                    uint32_t ah[4], al[4];
                    ldsm4(ah, bHi + kt * 32);
                    ldsm4(al, bLo + kt * 32);
                    mma_bf16(cxa[mt][0], ah, whi[0][kt]);
                    mma_bf16(cxa[mt][1], ah, whi[1][kt]);
                    mma_bf16(cxa[mt][0], ah, wlo[0][kt]);
                    mma_bf16(cxa[mt][1], ah, wlo[1][kt]);
                    mma_bf16(cxa[mt][0], al, whi[0][kt]);
                    mma_bf16(cxa[mt][1], al, whi[1][kt]);
                }
            }
        }

        __syncthreads();   // BOTTOM: h(t) visible for phase1(t+1)
    }
    if (!is_last && j == 0) publish(my_flag, T_LEN - 1);

    // ---- head on last layer ----
    if (is_last) {
#pragma unroll
        for (int q = 0; q < 3; q++) if (q < mc) {
            int p = q * 512 + j, ml = p >> 5, np = p & 31;
            sPre[ml * HID + 2 * np]     = hst[2 * q];
            sPre[ml * HID + 2 * np + 1] = hst[2 * q + 1];
        }
        __syncthreads();
        if (j < rows) {
            float s = 0.f;
#pragma unroll
            for (int k = 0; k < HID; k++) s += sPre[j * HID + k] * head_w[k];
            logits[mstart + j] = s + head_b[0];
        }
    }
}

extern "C" void kernel_launch(void* const* d_in, const int* in_sizes, int n_in,
                              void* d_out, int out_size) {
    const int*   x       = (const int*)d_in[0];
    const int*   lengths = (const int*)d_in[1];
    const float* emb     = (const float*)d_in[2];
    const float* Wi      = (const float*)d_in[3];
    const float* Wf      = (const float*)d_in[4];
    const float* Wg      = (const float*)d_in[5];
    const float* Wo      = (const float*)d_in[6];
    const float* bi      = (const float*)d_in[7];
    const float* bf      = (const float*)d_in[8];
    const float* bg      = (const float*)d_in[9];
    const float* bo      = (const float*)d_in[10];
    const float* init_h  = (const float*)d_in[11];
    const float* head_w  = (const float*)d_in[12];
    const float* head_b  = (const float*)d_in[13];
    float* logits = (float*)d_out;

    cudaFuncSetAttribute(lstm_fused, cudaFuncAttributeMaxDynamicSharedMemorySize,
                         SMEM_BYTES);

    gather_emb<<<(size_t)T_LEN * NB * 32 / 256, 256>>>(x, emb);
    lstm_fused<<<NLAY * NCTA_L, 512, SMEM_BYTES>>>(
        Wi, Wf, Wg, Wo, bi, bf, bg, bo,
        init_h, lengths, head_w, head_b, logits);
}

// round 7
// speedup vs baseline: 3.0347x; 1.1009x over previous
#include <cuda_runtime.h>
#include <cuda_bf16.h>
#include <cstdint>

#define T_LEN 1024
#define NB    1024
#define HID   64
#define NLAY  5
#define NCTA_L 29          // CTAs per layer (one wave: 5*29=145 <= 148)
#define N3    6            // first 6 CTAs: 48 rows (3 mtiles); other 23: 32 rows
#define XPITCH 72          // halfwords per x/h row plane (144B, odd 16B multiple)
#define PPITCH 264         // floats per pre-activation row
#define SX_PLANE (48 * XPITCH)            // 3456 halfwords per plane
#define XBUF_STRIDE (2 * SX_PLANE)        // hi+lo planes per x buffer
#define SH_BASE  (4 * XBUF_STRIDE)        // after 4 x-buffers
#define SPRE_OFF ((SH_BASE + 2 * SX_PLANE) * 2)   // byte offset of sPre
#define SMEM_BYTES (SPRE_OFF + 48 * PPITCH * 4)   // 119808 bytes

// Inter-layer activation sequences, bf16 hi/lo pairs packed 2-per-u32.
__device__ uint32_t g_seq[2][2][(size_t)T_LEN * NB * (HID / 2)];
__device__ int g_prog[NLAY * NCTA_L];

// ---------------- helpers ----------------
static __device__ __forceinline__ uint16_t bfbits(__nv_bfloat16 h) {
    return __bfloat16_as_ushort(h);
}
static __device__ __forceinline__ uint32_t bfsplit2(float a, float b, uint32_t* lo) {
    __nv_bfloat16 ha = __float2bfloat16(a), hb = __float2bfloat16(b);
    float ra = a - __bfloat162float(ha);
    float rb = b - __bfloat162float(hb);
    __nv_bfloat16 la = __float2bfloat16(ra), lb = __float2bfloat16(rb);
    *lo = ((uint32_t)bfbits(lb) << 16) | bfbits(la);
    return ((uint32_t)bfbits(hb) << 16) | bfbits(ha);
}
static __device__ __forceinline__ float bflo(uint32_t p) {
    return __bfloat162float(__ushort_as_bfloat16((uint16_t)(p & 0xFFFF)));
}
static __device__ __forceinline__ float bfhi(uint32_t p) {
    return __bfloat162float(__ushort_as_bfloat16((uint16_t)(p >> 16)));
}
static __device__ __forceinline__ void ldsm4(uint32_t a[4], uint32_t addr) {
    asm volatile("ldmatrix.sync.aligned.m8n8.x4.shared.b16 {%0,%1,%2,%3}, [%4];"
                 : "=r"(a[0]), "=r"(a[1]), "=r"(a[2]), "=r"(a[3]) : "r"(addr));
}
static __device__ __forceinline__ void mma_bf16(float c[4], const uint32_t a[4],
                                                const uint32_t b[2]) {
    asm volatile(
        "mma.sync.aligned.m16n8k16.row.col.f32.bf16.bf16.f32 "
        "{%0,%1,%2,%3}, {%4,%5,%6,%7}, {%8,%9}, {%0,%1,%2,%3};"
        : "+f"(c[0]), "+f"(c[1]), "+f"(c[2]), "+f"(c[3])
        : "r"(a[0]), "r"(a[1]), "r"(a[2]), "r"(a[3]), "r"(b[0]), "r"(b[1]));
}
static __device__ __forceinline__ void cp_async16(void* sdst, const void* gsrc) {
    unsigned sa = (unsigned)__cvta_generic_to_shared(sdst);
    asm volatile("cp.async.cg.shared.global [%0], [%1], 16;\n" :: "r"(sa), "l"(gsrc));
}
static __device__ __forceinline__ void cp_commit() {
    asm volatile("cp.async.commit_group;\n" ::: "memory");
}
static __device__ __forceinline__ void cp_wait3() {
    asm volatile("cp.async.wait_group 3;\n" ::: "memory");
}
static __device__ __forceinline__ float frcp(float x) {
    float r;
    asm("rcp.approx.ftz.f32 %0, %1;" : "=f"(r) : "f"(x));
    return r;
}
static __device__ __forceinline__ float tanh_f(float x) {
    x = fminf(fmaxf(x, -15.f), 15.f);
    float e = __expf(-2.f * x);
    return __fdividef(1.f - e, 1.f + e);
}
static __device__ __forceinline__ void publish(int* p, int v) {
    asm volatile("st.release.gpu.global.b32 [%0], %1;" :: "l"(p), "r"(v) : "memory");
}
static __device__ __forceinline__ int acq_load(const int* p) {
    int v;
    asm volatile("ld.acquire.gpu.global.b32 %0, [%1];" : "=r"(v) : "l"(p) : "memory");
    return v;
}

// ---------------- embedding gather -> g_seq[0] (+ flag reset) ----------------
__global__ void gather_emb(const int* __restrict__ x, const float* __restrict__ emb) {
    if (blockIdx.x == 0 && threadIdx.x < NLAY * NCTA_L) g_prog[threadIdx.x] = -1;
    size_t e = (size_t)blockIdx.x * 256 + threadIdx.x;   // over T*B*32
    int h2 = e & 31;
    int b  = (e >> 5) & (NB - 1);
    int t  = (int)(e >> 15);
    int xi = x[(size_t)b * T_LEN + t];
    float2 v = ((const float2*)(emb + (size_t)xi * HID))[h2];
    uint32_t lp, hp = bfsplit2(v.x, v.y, &lp);
    size_t o = ((size_t)t * NB + b) * (HID / 2) + h2;
    g_seq[0][0][o] = hp;
    g_seq[0][1][o] = lp;
}

// ---------------- fused one-wave pipelined LSTM ----------------
__global__ void __launch_bounds__(512, 1) lstm_fused(
    const float* __restrict__ Wi, const float* __restrict__ Wf,
    const float* __restrict__ Wg, const float* __restrict__ Wo,
    const float* __restrict__ bi, const float* __restrict__ bf,
    const float* __restrict__ bg, const float* __restrict__ bo,
    const float* __restrict__ init_h, const int* __restrict__ lengths,
    const float* __restrict__ head_w, const float* __restrict__ head_b,
    float* __restrict__ logits)
{
    extern __shared__ __align__(16) uint16_t sm[];
    float* sPre = (float*)((char*)sm + SPRE_OFF);

    const int layer = blockIdx.x / NCTA_L;
    const int gi    = blockIdx.x - layer * NCTA_L;
    const int mc     = (gi < N3) ? 3 : 2;              // mtiles in this CTA
    const int mstart = (gi < N3) ? 48 * gi : 288 + 32 * (gi - N3);
    const int rows   = 16 * mc;
    const int nchunk = 256 * mc;                        // 16B cp.async chunks per buf
    const int in_sel  = layer & 1;
    const int out_sel = in_sel ^ 1;
    const int is_last = (layer == NLAY - 1);
    const int has_src = (layer > 0);

    const int j    = threadIdx.x;
    const int lane = j & 31;
    const int w    = j >> 5;
    const int g    = lane >> 2;
    const int tig  = lane & 3;
    const int arow = lane & 15;
    const int acol = (lane >> 4) * 8;

    int* my_flag        = &g_prog[layer * NCTA_L + gi];
    const int* src_flag = &g_prog[(layer - 1) * NCTA_L + gi];
    int avail_c = -1;

    // ---- weight B-fragments (hi/lo) in registers, biases ----
    uint32_t whi[2][8][2], wlo[2][8][2];
    float be[2], bo_[2];
#pragma unroll
    for (int nt = 0; nt < 2; nt++) {
        int jo   = 16 * w + 8 * nt + g;
        int gate = jo >> 6, nc = jo & 63;
        const float* Wr =
            (gate == 0 ? Wi : gate == 1 ? Wf : gate == 2 ? Wg : Wo) +
            (size_t)(layer * HID + nc) * 128;
#pragma unroll
        for (int kt = 0; kt < 8; kt++) {
            int k0 = 16 * kt + 2 * tig;
            whi[nt][kt][0] = bfsplit2(Wr[k0],     Wr[k0 + 1], &wlo[nt][kt][0]);
            whi[nt][kt][1] = bfsplit2(Wr[k0 + 8], Wr[k0 + 9], &wlo[nt][kt][1]);
        }
        int je = 16 * w + 8 * nt + 2 * tig;
        int ge = je >> 6, ne = je & 63;
        be[nt] = (ge == 0 ? bi : ge == 1 ? bf : ge == 2 ? bg : bo)[layer * HID + ne];
        int jo2 = je + 1;
        int go2 = jo2 >> 6, no2 = jo2 & 63;
        bo_[nt] = (go2 == 0 ? bi : go2 == 1 ? bf : go2 == 2 ? bg : bo)[layer * HID + no2];
    }

    // ---- per-thread cell rows: p = q*512+j -> (ml = p>>5, np = p&31); mtile(q) == p>>9 pattern
    float cst[6];
    uint32_t hp_c[3], lp_c[3];
    int lenq[3];
    int lenmt[3];
#pragma unroll
    for (int q = 0; q < 3; q++) {
        lenq[q] = 0; lenmt[q] = 0;
        hp_c[q] = 0; lp_c[q] = 0;
        cst[2 * q] = 0.f; cst[2 * q + 1] = 0.f;
        if (q < mc) {
            int p = q * 512 + j, ml = p >> 5, np = p & 31;
            lenq[q] = lengths[mstart + ml];
            int L = 0;
#pragma unroll
            for (int r = 0; r < 16; r++) L = max(L, lengths[mstart + q * 16 + r]);
            lenmt[q] = L;
            float h0a = tanh_f(init_h[layer * HID + 2 * np]);
            float h0b = tanh_f(init_h[layer * HID + 2 * np + 1]);
            hp_c[q] = bfsplit2(h0a, h0b, &lp_c[q]);
        }
    }

    // prologue gate: wait for producer lead of ~13 steps
    if (has_src && j == 0) {
        int v = -1;
        while (v < 12) { v = acq_load(src_flag); if (v < 12) __nanosleep(40); }
        avail_c = v;
    }
    __syncthreads();

    // prefetch x(0..3) into buffers 0..3, one commit group each
#pragma unroll
    for (int tt = 0; tt < 4; tt++) {
#pragma unroll
        for (int q = 0; q < 2; q++) {
            int c = q * 512 + j;
            if (c < nchunk) {
                int r = c >> 4, sub = c & 15, hl = sub >> 3, ch = sub & 7;
                cp_async16(sm + tt * XBUF_STRIDE + hl * SX_PLANE + r * XPITCH + ch * 8,
                           &g_seq[in_sel][hl][((size_t)tt * NB + mstart + r) * 32 + ch * 4]);
            }
        }
        cp_commit();
    }

    // h0 into sH
#pragma unroll
    for (int q = 0; q < 3; q++) if (q < mc) {
        int p = q * 512 + j, ml = p >> 5, np = p & 31;
        *(uint32_t*)(sm + SH_BASE + 0 * SX_PLANE + ml * XPITCH + 2 * np) = hp_c[q];
        *(uint32_t*)(sm + SH_BASE + 1 * SX_PLANE + ml * XPITCH + 2 * np) = lp_c[q];
    }
    cp_wait3();          // x(0) landed
    __syncthreads();

    // prologue x-GEMM(0) from buffer 0 into cxa
    float cxa[3][2][4];
#pragma unroll
    for (int mt = 0; mt < 3; mt++) if (mt < mc) {
#pragma unroll
        for (int nt = 0; nt < 2; nt++) {
            cxa[mt][nt][0] = be[nt]; cxa[mt][nt][1] = bo_[nt];
            cxa[mt][nt][2] = be[nt]; cxa[mt][nt][3] = bo_[nt];
        }
        uint32_t bHi = (uint32_t)__cvta_generic_to_shared(
            sm + 0 * SX_PLANE + (mt * 16 + arow) * XPITCH + acol);
        uint32_t bLo = (uint32_t)__cvta_generic_to_shared(
            sm + 1 * SX_PLANE + (mt * 16 + arow) * XPITCH + acol);
#pragma unroll
        for (int kt = 0; kt < 4; kt++) {
            uint32_t ah[4], al[4];
            ldsm4(ah, bHi + kt * 32);
            ldsm4(al, bLo + kt * 32);
            mma_bf16(cxa[mt][0], ah, whi[0][kt]);
            mma_bf16(cxa[mt][1], ah, whi[1][kt]);
            mma_bf16(cxa[mt][0], ah, wlo[0][kt]);
            mma_bf16(cxa[mt][1], ah, wlo[1][kt]);
            mma_bf16(cxa[mt][0], al, whi[0][kt]);
            mma_bf16(cxa[mt][1], al, whi[1][kt]);
        }
    }

    const int col0 = 16 * w + 2 * tig;

    for (int t = 0; t < T_LEN; t++) {
        // early publish of h(t-1): stores were ordered by the bottom barrier
        if (!is_last && j == 0 && t >= 1) publish(my_flag, t - 1);

        // ======== PHASE 1: h-GEMM(t) (kt 4..7) into cxa, store pre ========
#pragma unroll
        for (int mt = 0; mt < 3; mt++) if (mt < mc && t < lenmt[mt]) {
            uint32_t bHi = (uint32_t)__cvta_generic_to_shared(
                sm + SH_BASE + 0 * SX_PLANE + (mt * 16 + arow) * XPITCH + acol);
            uint32_t bLo = (uint32_t)__cvta_generic_to_shared(
                sm + SH_BASE + 1 * SX_PLANE + (mt * 16 + arow) * XPITCH + acol);
#pragma unroll
            for (int kt = 4; kt < 8; kt++) {
                uint32_t ah[4], al[4];
                ldsm4(ah, bHi + (kt - 4) * 32);
                ldsm4(al, bLo + (kt - 4) * 32);
                mma_bf16(cxa[mt][0], ah, whi[0][kt]);
                mma_bf16(cxa[mt][1], ah, whi[1][kt]);
                mma_bf16(cxa[mt][0], ah, wlo[0][kt]);
                mma_bf16(cxa[mt][1], ah, wlo[1][kt]);
                mma_bf16(cxa[mt][0], al, whi[0][kt]);
                mma_bf16(cxa[mt][1], al, whi[1][kt]);
            }
            *(float2*)&sPre[(mt * 16 + g) * PPITCH + col0] =
                make_float2(cxa[mt][0][0], cxa[mt][0][1]);
            *(float2*)&sPre[(mt * 16 + g + 8) * PPITCH + col0] =
                make_float2(cxa[mt][0][2], cxa[mt][0][3]);
            *(float2*)&sPre[(mt * 16 + g) * PPITCH + col0 + 8] =
                make_float2(cxa[mt][1][0], cxa[mt][1][1]);
            *(float2*)&sPre[(mt * 16 + g + 8) * PPITCH + col0 + 8] =
                make_float2(cxa[mt][1][2], cxa[mt][1][3]);
        }
        // gate for x(t+4)
        if (has_src && j == 0) {
            int need = t + 4;
            if (need < T_LEN && avail_c < need) {
                int v = acq_load(src_flag);
                while (v < need) { __nanosleep(40); v = acq_load(src_flag); }
                avail_c = v;
            }
        }
        __syncthreads();   // MID: pre visible; acquire ordered before prefetch

        // ======== PHASE 2: prefetch x(t+4); interleaved x-GEMM(t+1) + cell(t) ========
        if (t + 4 < T_LEN) {
            int b = t & 3;
#pragma unroll
            for (int q = 0; q < 2; q++) {
                int c = q * 512 + j;
                if (c < nchunk) {
                    int r = c >> 4, sub = c & 15, hl = sub >> 3, ch = sub & 7;
                    cp_async16(sm + b * XBUF_STRIDE + hl * SX_PLANE + r * XPITCH + ch * 8,
                               &g_seq[in_sel][hl][((size_t)(t + 4) * NB + mstart + r) * 32 + ch * 4]);
                }
            }
        }
        cp_commit();
        cp_wait3();        // x(t+1) resident

        const int bx = (t + 1) & 3;
#pragma unroll
        for (int u = 0; u < 3; u++) if (u < mc) {
            // ---- x-GEMM(t+1) for mt=u (skipped when tile fully frozen) ----
            if (t + 1 < lenmt[u]) {
#pragma unroll
                for (int nt = 0; nt < 2; nt++) {
                    cxa[u][nt][0] = be[nt]; cxa[u][nt][1] = bo_[nt];
                    cxa[u][nt][2] = be[nt]; cxa[u][nt][3] = bo_[nt];
                }
                uint32_t bHi = (uint32_t)__cvta_generic_to_shared(
                    sm + bx * XBUF_STRIDE + 0 * SX_PLANE + (u * 16 + arow) * XPITCH + acol);
                uint32_t bLo = (uint32_t)__cvta_generic_to_shared(
                    sm + bx * XBUF_STRIDE + 1 * SX_PLANE + (u * 16 + arow) * XPITCH + acol);
#pragma unroll
                for (int kt = 0; kt < 4; kt++) {
                    uint32_t ah[4], al[4];
                    ldsm4(ah, bHi + kt * 32);
                    ldsm4(al, bLo + kt * 32);
                    mma_bf16(cxa[u][0], ah, whi[0][kt]);
                    mma_bf16(cxa[u][1], ah, whi[1][kt]);
                    mma_bf16(cxa[u][0], ah, wlo[0][kt]);
                    mma_bf16(cxa[u][1], ah, wlo[1][kt]);
                    mma_bf16(cxa[u][0], al, whi[0][kt]);
                    mma_bf16(cxa[u][1], al, whi[1][kt]);
                }
            }

            // ---- cell(t) for q=u (warp-uniform freeze-skip) ----
            int p = u * 512 + j, ml = p >> 5, np = p & 31;
            if (t < lenq[u]) {
                float2 pi2 = *(const float2*)&sPre[ml * PPITCH + 2 * np];
                float2 pf2 = *(const float2*)&sPre[ml * PPITCH + 64 + 2 * np];
                float2 pg2 = *(const float2*)&sPre[ml * PPITCH + 128 + 2 * np];
                float2 po2 = *(const float2*)&sPre[ml * PPITCH + 192 + 2 * np];
                // element 0
                float ea0 = __expf(-pi2.x), eb0 = __expf(-pf2.x);
                float ec0 = __expf(-po2.x), ed0 = __expf(-2.f * pg2.x);
                float u0 = 1.f + ea0, v0 = 1.f + eb0, w0 = 1.f + ec0, z0 = 1.f + ed0;
                float R10 = frcp(u0 * v0), R20 = frcp(w0 * z0);
                float si0 = R10 * v0, sf0 = R10 * u0;
                float so0 = R20 * z0, tg0 = 2.f * (R20 * w0) - 1.f;
                float c0n = sf0 * cst[2 * u] + si0 * tg0;
                // element 1
                float ea1 = __expf(-pi2.y), eb1 = __expf(-pf2.y);
                float ec1 = __expf(-po2.y), ed1 = __expf(-2.f * pg2.y);
                float u1 = 1.f + ea1, v1 = 1.f + eb1, w1 = 1.f + ec1, z1 = 1.f + ed1;
                float R11 = frcp(u1 * v1), R21 = frcp(w1 * z1);
                float si1 = R11 * v1, sf1 = R11 * u1;
                float so1 = R21 * z1, tg1 = 2.f * (R21 * w1) - 1.f;
                float c1n = sf1 * cst[2 * u + 1] + si1 * tg1;
                // tanh(c) paired across the two elements
                float cc0 = fminf(fmaxf(c0n, -15.f), 15.f);
                float cc1 = fminf(fmaxf(c1n, -15.f), 15.f);
                float e0 = __expf(-2.f * cc0), e1 = __expf(-2.f * cc1);
                float a0 = 1.f + e0, a1 = 1.f + e1;
                float R3 = frcp(a0 * a1);
                float th0 = (1.f - e0) * (R3 * a1);
                float th1 = (1.f - e1) * (R3 * a0);
                float h0n = so0 * th0, h1n = so1 * th1;
                cst[2 * u] = c0n; cst[2 * u + 1] = c1n;
                hp_c[u] = bfsplit2(h0n, h1n, &lp_c[u]);
                *(uint32_t*)(sm + SH_BASE + 0 * SX_PLANE + ml * XPITCH + 2 * np) = hp_c[u];
                *(uint32_t*)(sm + SH_BASE + 1 * SX_PLANE + ml * XPITCH + 2 * np) = lp_c[u];
            }
            if (!is_last) {
                size_t o = ((size_t)t * NB + mstart + ml) * 32 + np;
                g_seq[out_sel][0][o] = hp_c[u];
                g_seq[out_sel][1][o] = lp_c[u];
            }
        }

        __syncthreads();   // BOTTOM: h(t) visible for phase1(t+1)
    }
    if (!is_last && j == 0) publish(my_flag, T_LEN - 1);

    // ---- head on last layer (h recovered as hi+lo) ----
    if (is_last) {
#pragma unroll
        for (int q = 0; q < 3; q++) if (q < mc) {
            int p = q * 512 + j, ml = p >> 5, np = p & 31;
            sPre[ml * HID + 2 * np]     = bflo(hp_c[q]) + bflo(lp_c[q]);
            sPre[ml * HID + 2 * np + 1] = bfhi(hp_c[q]) + bfhi(lp_c[q]);
        }
        __syncthreads();
        if (j < rows) {
            float s = 0.f;
#pragma unroll
            for (int k = 0; k < HID; k++) s += sPre[j * HID + k] * head_w[k];
            logits[mstart + j] = s + head_b[0];
        }
    }
}

extern "C" void kernel_launch(void* const* d_in, const int* in_sizes, int n_in,
                              void* d_out, int out_size) {
    const int*   x       = (const int*)d_in[0];
    const int*   lengths = (const int*)d_in[1];
    const float* emb     = (const float*)d_in[2];
    const float* Wi      = (const float*)d_in[3];
    const float* Wf      = (const float*)d_in[4];
    const float* Wg      = (const float*)d_in[5];
    const float* Wo      = (const float*)d_in[6];
    const float* bi      = (const float*)d_in[7];
    const float* bf      = (const float*)d_in[8];
    const float* bg      = (const float*)d_in[9];
    const float* bo      = (const float*)d_in[10];
    const float* init_h  = (const float*)d_in[11];
    const float* head_w  = (const float*)d_in[12];
    const float* head_b  = (const float*)d_in[13];
    float* logits = (float*)d_out;

    cudaFuncSetAttribute(lstm_fused, cudaFuncAttributeMaxDynamicSharedMemorySize,
                         SMEM_BYTES);

    gather_emb<<<(size_t)T_LEN * NB * 32 / 256, 256>>>(x, emb);
    lstm_fused<<<NLAY * NCTA_L, 512, SMEM_BYTES>>>(
        Wi, Wf, Wg, Wo, bi, bf, bg, bo,
        init_h, lengths, head_w, head_b, logits);
}

// round 10
// speedup vs baseline: 3.6405x; 1.1996x over previous
#include <cuda_runtime.h>
#include <cuda_bf16.h>
#include <cstdint>

#define T_LEN 1024
#define NB    1024
#define HID   64
#define NLAY  5
#define NCTA_L 29          // CTAs per layer (one wave: 5*29=145 <= 148)
#define N3    6            // first 6 CTAs: 48 rows (3 mtiles); other 23: 32 rows
#define XPITCH 72          // halfwords per x/h row plane (144B, odd 16B multiple)
#define PPITCH 264         // floats per pre-activation row
#define SX_PLANE (48 * XPITCH)            // 3456 halfwords per plane
#define XBUF_STRIDE (2 * SX_PLANE)        // hi+lo planes per x buffer
#define SH_BASE  (4 * XBUF_STRIDE)        // after 4 x-buffers
#define SPRE_OFF ((SH_BASE + 2 * SX_PLANE) * 2)   // byte offset of sPre
#define SPERM_OFF (SPRE_OFF + 48 * PPITCH * 4)    // byte offset of sPerm/sLen
#define SMEM_BYTES (SPERM_OFF + 48 * 2 * 4)       // + perm & len arrays
#define GPLANE ((size_t)T_LEN * NB * 32)          // u32 elems per hi/lo plane

// Inter-layer activation sequences, bf16 hi/lo pairs packed 2-per-u32.
__device__ uint32_t g_seq[2][2][GPLANE];
__device__ int g_prog[NLAY * NCTA_L];

// ---------------- helpers ----------------
static __device__ __forceinline__ uint16_t bfbits(__nv_bfloat16 h) {
    return __bfloat16_as_ushort(h);
}
static __device__ __forceinline__ uint32_t bfsplit2(float a, float b, uint32_t* lo) {
    __nv_bfloat16 ha = __float2bfloat16(a), hb = __float2bfloat16(b);
    float ra = a - __bfloat162float(ha);
    float rb = b - __bfloat162float(hb);
    __nv_bfloat16 la = __float2bfloat16(ra), lb = __float2bfloat16(rb);
    *lo = ((uint32_t)bfbits(lb) << 16) | bfbits(la);
    return ((uint32_t)bfbits(hb) << 16) | bfbits(ha);
}
static __device__ __forceinline__ float bflo(uint32_t p) {
    return __bfloat162float(__ushort_as_bfloat16((uint16_t)(p & 0xFFFF)));
}
static __device__ __forceinline__ float bfhi(uint32_t p) {
    return __bfloat162float(__ushort_as_bfloat16((uint16_t)(p >> 16)));
}
static __device__ __forceinline__ void ldsm4(uint32_t a[4], uint32_t addr) {
    asm volatile("ldmatrix.sync.aligned.m8n8.x4.shared.b16 {%0,%1,%2,%3}, [%4];"
                 : "=r"(a[0]), "=r"(a[1]), "=r"(a[2]), "=r"(a[3]) : "r"(addr));
}
static __device__ __forceinline__ void mma_bf16(float c[4], const uint32_t a[4],
                                                const uint32_t b[2]) {
    asm volatile(
        "mma.sync.aligned.m16n8k16.row.col.f32.bf16.bf16.f32 "
        "{%0,%1,%2,%3}, {%4,%5,%6,%7}, {%8,%9}, {%0,%1,%2,%3};"
        : "+f"(c[0]), "+f"(c[1]), "+f"(c[2]), "+f"(c[3])
        : "r"(a[0]), "r"(a[1]), "r"(a[2]), "r"(a[3]), "r"(b[0]), "r"(b[1]));
}
static __device__ __forceinline__ void cp_async16(void* sdst, const void* gsrc) {
    unsigned sa = (unsigned)__cvta_generic_to_shared(sdst);
    asm volatile("cp.async.cg.shared.global [%0], [%1], 16;\n" :: "r"(sa), "l"(gsrc));
}
static __device__ __forceinline__ void cp_async16_s(unsigned sa, const void* gsrc) {
    asm volatile("cp.async.cg.shared.global [%0], [%1], 16;\n" :: "r"(sa), "l"(gsrc));
}
static __device__ __forceinline__ void cp_commit() {
    asm volatile("cp.async.commit_group;\n" ::: "memory");
}
static __device__ __forceinline__ void cp_wait3() {
    asm volatile("cp.async.wait_group 3;\n" ::: "memory");
}
static __device__ __forceinline__ float frcp(float x) {
    float r;
    asm("rcp.approx.ftz.f32 %0, %1;" : "=f"(r) : "f"(x));
    return r;
}
static __device__ __forceinline__ float tanh_f(float x) {
    x = fminf(fmaxf(x, -15.f), 15.f);
    float e = __expf(-2.f * x);
    return __fdividef(1.f - e, 1.f + e);
}
static __device__ __forceinline__ void publish(int* p, int v) {
    asm volatile("st.release.gpu.global.b32 [%0], %1;" :: "l"(p), "r"(v) : "memory");
}
static __device__ __forceinline__ int acq_load(const int* p) {
    int v;
    asm volatile("ld.acquire.gpu.global.b32 %0, [%1];" : "=r"(v) : "l"(p) : "memory");
    return v;
}

// ---------------- embedding gather -> g_seq[0] (+ flag reset) ----------------
__global__ void gather_emb(const int* __restrict__ x, const float* __restrict__ emb) {
    if (blockIdx.x == 0 && threadIdx.x < NLAY * NCTA_L) g_prog[threadIdx.x] = -1;
    size_t e = (size_t)blockIdx.x * 256 + threadIdx.x;   // over T*B*32
    int h2 = e & 31;
    int b  = (e >> 5) & (NB - 1);
    int t  = (int)(e >> 15);
    int xi = x[(size_t)b * T_LEN + t];
    float2 v = ((const float2*)(emb + (size_t)xi * HID))[h2];
    uint32_t lp, hp = bfsplit2(v.x, v.y, &lp);
    size_t o = ((size_t)t * NB + b) * (HID / 2) + h2;
    g_seq[0][0][o] = hp;
    g_seq[0][1][o] = lp;
}

// ---------------- fused one-wave pipelined LSTM ----------------
__global__ void __launch_bounds__(512, 1) lstm_fused(
    const float* __restrict__ Wi, const float* __restrict__ Wf,
    const float* __restrict__ Wg, const float* __restrict__ Wo,
    const float* __restrict__ bi, const float* __restrict__ bf,
    const float* __restrict__ bg, const float* __restrict__ bo,
    const float* __restrict__ init_h, const int* __restrict__ lengths,
    const float* __restrict__ head_w, const float* __restrict__ head_b,
    float* __restrict__ logits)
{
    extern __shared__ __align__(16) uint16_t sm[];
    float* sPre = (float*)((char*)sm + SPRE_OFF);
    int* sPerm = (int*)((char*)sm + SPERM_OFF);
    int* sLen  = sPerm + 48;

    const int layer = blockIdx.x / NCTA_L;
    const int gi    = blockIdx.x - layer * NCTA_L;
    const int mc     = (gi < N3) ? 3 : 2;              // mtiles in this CTA
    const int mstart = (gi < N3) ? 48 * gi : 288 + 32 * (gi - N3);
    const int rows   = 16 * mc;
    const int nchunk = 256 * mc;                        // 16B cp.async chunks per buf
    const int in_sel  = layer & 1;
    const int out_sel = in_sel ^ 1;
    const int is_last = (layer == NLAY - 1);
    const int has_src = (layer > 0);

    const int j    = threadIdx.x;
    const int lane = j & 31;
    const int w    = j >> 5;
    const int g    = lane >> 2;
    const int tig  = lane & 3;
    const int arow = lane & 15;
    const int acol = (lane >> 4) * 8;

    int* my_flag        = &g_prog[layer * NCTA_L + gi];
    const int* src_flag = &g_prog[(layer - 1) * NCTA_L + gi];
    int avail_c = -1;

    // ---- sort rows by length (ascending): rank sort, deterministic ----
    if (j < rows) {
        int Lr = lengths[mstart + j];
        int rank = 0;
        for (int s = 0; s < rows; s++) {
            int Ls = lengths[mstart + s];
            rank += (Ls < Lr) || (Ls == Lr && s < j);
        }
        sPerm[rank] = j;
        sLen[rank]  = Lr;
    }

    // ---- weight B-fragments (hi/lo) in registers, biases ----
    uint32_t whi[2][8][2], wlo[2][8][2];
    float be[2], bo_[2];
#pragma unroll
    for (int nt = 0; nt < 2; nt++) {
        int jo   = 16 * w + 8 * nt + g;
        int gate = jo >> 6, nc = jo & 63;
        const float* Wr =
            (gate == 0 ? Wi : gate == 1 ? Wf : gate == 2 ? Wg : Wo) +
            (size_t)(layer * HID + nc) * 128;
#pragma unroll
        for (int kt = 0; kt < 8; kt++) {
            int k0 = 16 * kt + 2 * tig;
            whi[nt][kt][0] = bfsplit2(Wr[k0],     Wr[k0 + 1], &wlo[nt][kt][0]);
            whi[nt][kt][1] = bfsplit2(Wr[k0 + 8], Wr[k0 + 9], &wlo[nt][kt][1]);
        }
        int je = 16 * w + 8 * nt + 2 * tig;
        int ge = je >> 6, ne = je & 63;
        be[nt] = (ge == 0 ? bi : ge == 1 ? bf : ge == 2 ? bg : bo)[layer * HID + ne];
        int jo2 = je + 1;
        int go2 = jo2 >> 6, no2 = jo2 & 63;
        bo_[nt] = (go2 == 0 ? bi : go2 == 1 ? bf : go2 == 2 ? bg : bo)[layer * HID + no2];
    }
    __syncthreads();   // sPerm/sLen ready

    // ---- per-thread cell rows (sorted order): p = q*512+j -> (ml, np) ----
    float cst[6];
    uint32_t hp_c[3], lp_c[3];
    int lenq[3], lenmt[3];
    uint32_t* gout[3];
#pragma unroll
    for (int q = 0; q < 3; q++) {
        lenq[q] = 0; lenmt[q] = 0;
        hp_c[q] = 0; lp_c[q] = 0;
        cst[2 * q] = 0.f; cst[2 * q + 1] = 0.f;
        gout[q] = nullptr;
        if (q < mc) {
            int p = q * 512 + j, ml = p >> 5, np = p & 31;
            lenq[q]  = sLen[ml];
            lenmt[q] = sLen[q * 16 + 15];   // max of sorted tile
            float h0a = tanh_f(init_h[layer * HID + 2 * np]);
            float h0b = tanh_f(init_h[layer * HID + 2 * np + 1]);
            hp_c[q] = bfsplit2(h0a, h0b, &lp_c[q]);
            gout[q] = &g_seq[out_sel][0][(size_t)(mstart + sPerm[ml]) * 32 + np];
        }
    }

    // ---- x source pointers (per chunk), positioned at t=4; smem dst bases ----
    const uint32_t* xsrc[2];
    unsigned xdst[2];
    int xlen[2];
#pragma unroll
    for (int q = 0; q < 2; q++) {
        xsrc[q] = nullptr; xlen[q] = 0; xdst[q] = 0;
        int c = q * 512 + j;
        if (c < nchunk) {
            int r = c >> 4, sub = c & 15, hl = sub >> 3, ch = sub & 7;
            xlen[q] = sLen[r];
            xsrc[q] = &g_seq[in_sel][hl][((size_t)4 * NB + mstart + sPerm[r]) * 32 + ch * 4];
            xdst[q] = (unsigned)__cvta_generic_to_shared(
                sm + hl * SX_PLANE + r * XPITCH + ch * 8);
        }
    }

    // prologue gate: wait for producer lead of ~13 steps
    if (has_src && j == 0) {
        int v = -1;
        while (v < 12) { v = acq_load(src_flag); if (v < 12) __nanosleep(40); }
        avail_c = v;
    }
    __syncthreads();   // ALL threads held until producer is ahead (was missing in R9!)

    // prefetch x(0..3) (permuted source rows), one commit group each
#pragma unroll
    for (int tt = 0; tt < 4; tt++) {
#pragma unroll
        for (int q = 0; q < 2; q++) {
            int c = q * 512 + j;
            if (c < nchunk) {
                int r = c >> 4, sub = c & 15, hl = sub >> 3, ch = sub & 7;
                cp_async16(sm + tt * XBUF_STRIDE + hl * SX_PLANE + r * XPITCH + ch * 8,
                           &g_seq[in_sel][hl][((size_t)tt * NB + mstart + sPerm[r]) * 32 + ch * 4]);
            }
        }
        cp_commit();
    }

    // h0 into sH
#pragma unroll
    for (int q = 0; q < 3; q++) if (q < mc) {
        int p = q * 512 + j, ml = p >> 5, np = p & 31;
        *(uint32_t*)(sm + SH_BASE + 0 * SX_PLANE + ml * XPITCH + 2 * np) = hp_c[q];
        *(uint32_t*)(sm + SH_BASE + 1 * SX_PLANE + ml * XPITCH + 2 * np) = lp_c[q];
    }
    cp_wait3();          // x(0) landed
    __syncthreads();

    // prologue x-GEMM(0) from buffer 0 into cxa
    float cxa[3][2][4];
#pragma unroll
    for (int mt = 0; mt < 3; mt++) if (mt < mc) {
#pragma unroll
        for (int nt = 0; nt < 2; nt++) {
            cxa[mt][nt][0] = be[nt]; cxa[mt][nt][1] = bo_[nt];
            cxa[mt][nt][2] = be[nt]; cxa[mt][nt][3] = bo_[nt];
        }
        uint32_t bHi = (uint32_t)__cvta_generic_to_shared(
            sm + 0 * SX_PLANE + (mt * 16 + arow) * XPITCH + acol);
        uint32_t bLo = (uint32_t)__cvta_generic_to_shared(
            sm + 1 * SX_PLANE + (mt * 16 + arow) * XPITCH + acol);
#pragma unroll
        for (int kt = 0; kt < 4; kt++) {
            uint32_t ah[4], al[4];
            ldsm4(ah, bHi + kt * 32);
            ldsm4(al, bLo + kt * 32);
            mma_bf16(cxa[mt][0], ah, whi[0][kt]);
            mma_bf16(cxa[mt][1], ah, whi[1][kt]);
            mma_bf16(cxa[mt][0], ah, wlo[0][kt]);
            mma_bf16(cxa[mt][1], ah, wlo[1][kt]);
            mma_bf16(cxa[mt][0], al, whi[0][kt]);
            mma_bf16(cxa[mt][1], al, whi[1][kt]);
        }
    }

    const int col0 = 16 * w + 2 * tig;

    for (int t = 0; t < T_LEN; t++) {
        // early publish of h(t-1): stores were ordered by the bottom barrier
        if (!is_last && j == 0 && t >= 1) publish(my_flag, t - 1);

        // ======== PHASE 1: h-GEMM(t) (kt 4..7) into cxa, store pre ========
#pragma unroll
        for (int mt = 0; mt < 3; mt++) if (mt < mc && t < lenmt[mt]) {
            uint32_t bHi = (uint32_t)__cvta_generic_to_shared(
                sm + SH_BASE + 0 * SX_PLANE + (mt * 16 + arow) * XPITCH + acol);
            uint32_t bLo = (uint32_t)__cvta_generic_to_shared(
                sm + SH_BASE + 1 * SX_PLANE + (mt * 16 + arow) * XPITCH + acol);
#pragma unroll
            for (int kt = 4; kt < 8; kt++) {
                uint32_t ah[4], al[4];
                ldsm4(ah, bHi + (kt - 4) * 32);
                ldsm4(al, bLo + (kt - 4) * 32);
                mma_bf16(cxa[mt][0], ah, whi[0][kt]);
                mma_bf16(cxa[mt][1], ah, whi[1][kt]);
                mma_bf16(cxa[mt][0], ah, wlo[0][kt]);
                mma_bf16(cxa[mt][1], ah, wlo[1][kt]);
                mma_bf16(cxa[mt][0], al, whi[0][kt]);
                mma_bf16(cxa[mt][1], al, whi[1][kt]);
            }
            *(float2*)&sPre[(mt * 16 + g) * PPITCH + col0] =
                make_float2(cxa[mt][0][0], cxa[mt][0][1]);
            *(float2*)&sPre[(mt * 16 + g + 8) * PPITCH + col0] =
                make_float2(cxa[mt][0][2], cxa[mt][0][3]);
            *(float2*)&sPre[(mt * 16 + g) * PPITCH + col0 + 8] =
                make_float2(cxa[mt][1][0], cxa[mt][1][1]);
            *(float2*)&sPre[(mt * 16 + g + 8) * PPITCH + col0 + 8] =
                make_float2(cxa[mt][1][2], cxa[mt][1][3]);
        }
        // gate for x(t+4)
        if (has_src && j == 0) {
            int need = t + 4;
            if (need < T_LEN && avail_c < need) {
                int v = acq_load(src_flag);
                while (v < need) { __nanosleep(40); v = acq_load(src_flag); }
                avail_c = v;
            }
        }
        __syncthreads();   // MID: pre visible; acquire ordered before prefetch

        // ======== PHASE 2: prefetch x(t+4); interleaved x-GEMM(t+1) + cell(t) ========
        if (t + 4 < T_LEN) {
            unsigned boff = (unsigned)(t & 3) * (XBUF_STRIDE * 2);
#pragma unroll
            for (int q = 0; q < 2; q++)
                if (t + 4 < xlen[q]) cp_async16_s(xdst[q] + boff, xsrc[q]);
        }
#pragma unroll
        for (int q = 0; q < 2; q++) xsrc[q] += NB * 32;
        cp_commit();
        cp_wait3();        // x(t+1) resident

        const int bx = (t + 1) & 3;
#pragma unroll
        for (int u = 0; u < 3; u++) if (u < mc) {
            // ---- x-GEMM(t+1) for mt=u (skipped when tile fully frozen) ----
            if (t + 1 < lenmt[u]) {
#pragma unroll
                for (int nt = 0; nt < 2; nt++) {
                    cxa[u][nt][0] = be[nt]; cxa[u][nt][1] = bo_[nt];
                    cxa[u][nt][2] = be[nt]; cxa[u][nt][3] = bo_[nt];
                }
                uint32_t bHi = (uint32_t)__cvta_generic_to_shared(
                    sm + bx * XBUF_STRIDE + 0 * SX_PLANE + (u * 16 + arow) * XPITCH + acol);
                uint32_t bLo = (uint32_t)__cvta_generic_to_shared(
                    sm + bx * XBUF_STRIDE + 1 * SX_PLANE + (u * 16 + arow) * XPITCH + acol);
#pragma unroll
                for (int kt = 0; kt < 4; kt++) {
                    uint32_t ah[4], al[4];
                    ldsm4(ah, bHi + kt * 32);
                    ldsm4(al, bLo + kt * 32);
                    mma_bf16(cxa[u][0], ah, whi[0][kt]);
                    mma_bf16(cxa[u][1], ah, whi[1][kt]);
                    mma_bf16(cxa[u][0], ah, wlo[0][kt]);
                    mma_bf16(cxa[u][1], ah, wlo[1][kt]);
                    mma_bf16(cxa[u][0], al, whi[0][kt]);
                    mma_bf16(cxa[u][1], al, whi[1][kt]);
                }
            }

            // ---- cell(t) for q=u (warp-uniform freeze-skip) ----
            if (t < lenq[u]) {
                int p = u * 512 + j, ml = p >> 5, np = p & 31;
                float2 pi2 = *(const float2*)&sPre[ml * PPITCH + 2 * np];
                float2 pf2 = *(const float2*)&sPre[ml * PPITCH + 64 + 2 * np];
                float2 pg2 = *(const float2*)&sPre[ml * PPITCH + 128 + 2 * np];
                float2 po2 = *(const float2*)&sPre[ml * PPITCH + 192 + 2 * np];
                // element 0
                float ea0 = __expf(-pi2.x), eb0 = __expf(-pf2.x);
                float ec0 = __expf(-po2.x), ed0 = __expf(-2.f * pg2.x);
                float u0 = 1.f + ea0, v0 = 1.f + eb0, w0 = 1.f + ec0, z0 = 1.f + ed0;
                float R10 = frcp(u0 * v0), R20 = frcp(w0 * z0);
                float si0 = R10 * v0, sf0 = R10 * u0;
                float so0 = R20 * z0, tg0 = 2.f * (R20 * w0) - 1.f;
                float c0n = sf0 * cst[2 * u] + si0 * tg0;
                // element 1
                float ea1 = __expf(-pi2.y), eb1 = __expf(-pf2.y);
                float ec1 = __expf(-po2.y), ed1 = __expf(-2.f * pg2.y);
                float u1 = 1.f + ea1, v1 = 1.f + eb1, w1 = 1.f + ec1, z1 = 1.f + ed1;
                float R11 = frcp(u1 * v1), R21 = frcp(w1 * z1);
                float si1 = R11 * v1, sf1 = R11 * u1;
                float so1 = R21 * z1, tg1 = 2.f * (R21 * w1) - 1.f;
                float c1n = sf1 * cst[2 * u + 1] + si1 * tg1;
                // tanh(c) paired across the two elements
                float cc0 = fminf(fmaxf(c0n, -15.f), 15.f);
                float cc1 = fminf(fmaxf(c1n, -15.f), 15.f);
                float e0 = __expf(-2.f * cc0), e1 = __expf(-2.f * cc1);
                float a0 = 1.f + e0, a1 = 1.f + e1;
                float R3 = frcp(a0 * a1);
                float th0 = (1.f - e0) * (R3 * a1);
                float th1 = (1.f - e1) * (R3 * a0);
                float h0n = so0 * th0, h1n = so1 * th1;
                cst[2 * u] = c0n; cst[2 * u + 1] = c1n;
                hp_c[u] = bfsplit2(h0n, h1n, &lp_c[u]);
                *(uint32_t*)(sm + SH_BASE + 0 * SX_PLANE + ml * XPITCH + 2 * np) = hp_c[u];
                *(uint32_t*)(sm + SH_BASE + 1 * SX_PLANE + ml * XPITCH + 2 * np) = lp_c[u];
                if (!is_last) {
                    gout[u][0]      = hp_c[u];
                    gout[u][GPLANE] = lp_c[u];
                }
            }
        }
#pragma unroll
        for (int q = 0; q < 3; q++) if (q < mc) gout[q] += NB * 32;

        __syncthreads();   // BOTTOM: h(t) visible for phase1(t+1)
    }
    if (!is_last && j == 0) publish(my_flag, T_LEN - 1);

    // ---- head on last layer (h recovered as hi+lo; un-permute rows) ----
    if (is_last) {
#pragma unroll
        for (int q = 0; q < 3; q++) if (q < mc) {
            int p = q * 512 + j, ml = p >> 5, np = p & 31;
            sPre[ml * HID + 2 * np]     = bflo(hp_c[q]) + bflo(lp_c[q]);
            sPre[ml * HID + 2 * np + 1] = bfhi(hp_c[q]) + bfhi(lp_c[q]);
        }
        __syncthreads();
        if (j < rows) {
            float s = 0.f;
#pragma unroll
            for (int k = 0; k < HID; k++) s += sPre[j * HID + k] * head_w[k];
            logits[mstart + sPerm[j]] = s + head_b[0];
        }
    }
}

extern "C" void kernel_launch(void* const* d_in, const int* in_sizes, int n_in,
                              void* d_out, int out_size) {
    const int*   x       = (const int*)d_in[0];
    const int*   lengths = (const int*)d_in[1];
    const float* emb     = (const float*)d_in[2];
    const float* Wi      = (const float*)d_in[3];
    const float* Wf      = (const float*)d_in[4];
    const float* Wg      = (const float*)d_in[5];
    const float* Wo      = (const float*)d_in[6];
    const float* bi      = (const float*)d_in[7];
    const float* bf      = (const float*)d_in[8];
    const float* bg      = (const float*)d_in[9];
    const float* bo      = (const float*)d_in[10];
    const float* init_h  = (const float*)d_in[11];
    const float* head_w  = (const float*)d_in[12];
    const float* head_b  = (const float*)d_in[13];
    float* logits = (float*)d_out;

    cudaFuncSetAttribute(lstm_fused, cudaFuncAttributeMaxDynamicSharedMemorySize,
                         SMEM_BYTES);

    gather_emb<<<(size_t)T_LEN * NB * 32 / 256, 256>>>(x, emb);
    lstm_fused<<<NLAY * NCTA_L, 512, SMEM_BYTES>>>(
        Wi, Wf, Wg, Wo, bi, bf, bg, bo,
        init_h, lengths, head_w, head_b, logits);
}